// round 1
// baseline (speedup 1.0000x reference)
#include <cuda_runtime.h>
#include <math.h>
#include <stdint.h>

// Problem constants
#define B_   4
#define S_   2048
#define D_   1024
#define H_   16
#define DH_  64
#define FF_  4096
#define NTOK (B_ * S_)   // 8192

// ---------------------------------------------------------------------------
// Scratch buffers (device globals — no runtime allocation allowed)
// ---------------------------------------------------------------------------
__device__ float g_q[(size_t)NTOK * D_];
__device__ float g_k[(size_t)NTOK * D_];    // reused as (x + atted) after flash
__device__ float g_v[(size_t)NTOK * D_];    // reused as (x1 + ff) after flash
__device__ float g_ctx[(size_t)NTOK * D_];
__device__ float g_x1[(size_t)NTOK * D_];
__device__ float g_hb[(size_t)NTOK * FF_];

// ---------------------------------------------------------------------------
// SGEMM: C[M,N] = A[M,K] @ W[K,N] + bias (+ optional relu / residual)
// 128x128 tile, BK=8, 256 threads, 8x8 per thread.
// EPI: 0 = bias, 1 = bias+relu, 2 = bias+residual
// ---------------------------------------------------------------------------
#define GBM 128
#define GBN 128
#define GBK 8

template <int EPI>
__global__ __launch_bounds__(256) void sgemm_kernel(
    const float* __restrict__ A, const float* __restrict__ W,
    const float* __restrict__ bias, const float* __restrict__ res,
    float* __restrict__ C, int M, int N, int K)
{
    __shared__ float As[GBK][GBM];
    __shared__ float Ws[GBK][GBN];

    const int tid = threadIdx.x;
    const int tx = tid & 15;
    const int ty = tid >> 4;
    const int bm = blockIdx.y * GBM;
    const int bn = blockIdx.x * GBN;

    // A tile loader: 128 rows x 8 cols, one float4 per thread
    const int a_row = tid >> 1;
    const int a_col = (tid & 1) << 2;
    // W tile loader: 8 rows x 128 cols, one float4 per thread
    const int w_row = tid >> 5;
    const int w_col = (tid & 31) << 2;

    const float* Ag = A + (size_t)(bm + a_row) * K + a_col;
    const float* Wg = W + (size_t)w_row * N + bn + w_col;

    float acc[8][8];
#pragma unroll
    for (int i = 0; i < 8; i++)
#pragma unroll
        for (int j = 0; j < 8; j++) acc[i][j] = 0.f;

    for (int k0 = 0; k0 < K; k0 += GBK) {
        float4 av = *(const float4*)(Ag + k0);
        float4 wv = *(const float4*)(Wg + (size_t)k0 * N);
        As[a_col + 0][a_row] = av.x;
        As[a_col + 1][a_row] = av.y;
        As[a_col + 2][a_row] = av.z;
        As[a_col + 3][a_row] = av.w;
        *(float4*)&Ws[w_row][w_col] = wv;
        __syncthreads();

#pragma unroll
        for (int kk = 0; kk < GBK; kk++) {
            float a[8], b[8];
            *(float4*)(a)     = *(const float4*)&As[kk][ty * 4];
            *(float4*)(a + 4) = *(const float4*)&As[kk][64 + ty * 4];
            *(float4*)(b)     = *(const float4*)&Ws[kk][tx * 4];
            *(float4*)(b + 4) = *(const float4*)&Ws[kk][64 + tx * 4];
#pragma unroll
            for (int i = 0; i < 8; i++)
#pragma unroll
                for (int j = 0; j < 8; j++) acc[i][j] = fmaf(a[i], b[j], acc[i][j]);
        }
        __syncthreads();
    }

    // Epilogue
#pragma unroll
    for (int i = 0; i < 8; i++) {
        const int r = bm + ((i < 4) ? (ty * 4 + i) : (64 + ty * 4 + i - 4));
#pragma unroll
        for (int jh = 0; jh < 2; jh++) {
            const int cbase = bn + jh * 64 + tx * 4;
            float4 bi = *(const float4*)(bias + cbase);
            float o0 = acc[i][jh * 4 + 0] + bi.x;
            float o1 = acc[i][jh * 4 + 1] + bi.y;
            float o2 = acc[i][jh * 4 + 2] + bi.z;
            float o3 = acc[i][jh * 4 + 3] + bi.w;
            if (EPI == 1) {
                o0 = fmaxf(o0, 0.f); o1 = fmaxf(o1, 0.f);
                o2 = fmaxf(o2, 0.f); o3 = fmaxf(o3, 0.f);
            }
            if (EPI == 2) {
                float4 rv = *(const float4*)(res + (size_t)r * N + cbase);
                o0 += rv.x; o1 += rv.y; o2 += rv.z; o3 += rv.w;
            }
            float4 ov = make_float4(o0, o1, o2, o3);
            *(float4*)(C + (size_t)r * N + cbase) = ov;
        }
    }
}

// ---------------------------------------------------------------------------
// Flash attention: one CTA per (b,h, 64-query tile). 64-key tiles streamed.
// Smem: Qt (transposed) 16KB + KtP (K transposed, then P row-major) 16KB +
//       V row-major 16KB = 48KB exactly (static limit).
// Threads 16x16; each owns a 4x4 micro-tile of the 64x64 score / output.
// ---------------------------------------------------------------------------
__global__ __launch_bounds__(256) void flash_kernel(
    const float* __restrict__ q, const float* __restrict__ k,
    const float* __restrict__ v, const unsigned char* __restrict__ mask,
    float* __restrict__ ctx)
{
    __shared__ float Qt[64 * 64];   // Qt[d*64 + r]
    __shared__ float KtP[64 * 64];  // Kt[d*64 + c]  then  P[r*64 + c]
    __shared__ float Vs[64 * 64];   // V[kk*64 + c]

    const int tid = threadIdx.x;
    const int tx = tid & 15;
    const int ty = tid >> 4;
    const int bh = blockIdx.y;           // b*H + h
    const int b  = bh >> 4;              // H = 16
    const int h  = bh & 15;
    const int q0 = blockIdx.x * 64;
    const size_t base = (size_t)b * S_ * D_ + (size_t)h * DH_;
    const unsigned char* mrow = mask + (size_t)b * S_;

    // Load Q tile transposed: Qt[d][r]
    for (int s4 = tid; s4 < 64 * 16; s4 += 256) {
        const int tok = s4 >> 4;
        const int d = (s4 & 15) << 2;
        float4 qv = *(const float4*)(q + base + (size_t)(q0 + tok) * D_ + d);
        Qt[(d + 0) * 64 + tok] = qv.x;
        Qt[(d + 1) * 64 + tok] = qv.y;
        Qt[(d + 2) * 64 + tok] = qv.z;
        Qt[(d + 3) * 64 + tok] = qv.w;
    }

    float o[4][4];
    float m_i[4], l_i[4];
#pragma unroll
    for (int i = 0; i < 4; i++) {
        m_i[i] = -1e30f;
        l_i[i] = 0.f;
#pragma unroll
        for (int j = 0; j < 4; j++) o[i][j] = 0.f;
    }

    for (int kt = 0; kt < S_; kt += 64) {
        __syncthreads();  // protect KtP/Vs from previous-iter readers (and Qt on iter0 path)

        // Load K tile transposed + V tile row-major
        for (int s4 = tid; s4 < 64 * 16; s4 += 256) {
            const int tok = s4 >> 4;
            const int d = (s4 & 15) << 2;
            float4 kv = *(const float4*)(k + base + (size_t)(kt + tok) * D_ + d);
            KtP[(d + 0) * 64 + tok] = kv.x;
            KtP[(d + 1) * 64 + tok] = kv.y;
            KtP[(d + 2) * 64 + tok] = kv.z;
            KtP[(d + 3) * 64 + tok] = kv.w;
            float4 vv = *(const float4*)(v + base + (size_t)(kt + tok) * D_ + d);
            *(float4*)&Vs[tok * 64 + d] = vv;
        }
        __syncthreads();

        // s = Q @ K^T  (raw dot products)
        float s[4][4];
#pragma unroll
        for (int i = 0; i < 4; i++)
#pragma unroll
            for (int j = 0; j < 4; j++) s[i][j] = 0.f;

#pragma unroll 4
        for (int d = 0; d < 64; d++) {
            float4 aq = *(const float4*)&Qt[d * 64 + ty * 4];
            float4 bk4 = *(const float4*)&KtP[d * 64 + tx * 4];
            float a[4] = {aq.x, aq.y, aq.z, aq.w};
            float bb[4] = {bk4.x, bk4.y, bk4.z, bk4.w};
#pragma unroll
            for (int i = 0; i < 4; i++)
#pragma unroll
                for (int j = 0; j < 4; j++) s[i][j] = fmaf(a[i], bb[j], s[i][j]);
        }

        // scale + mask
#pragma unroll
        for (int j = 0; j < 4; j++) {
            const bool msk = mrow[kt + tx * 4 + j] != 0;
#pragma unroll
            for (int i = 0; i < 4; i++)
                s[i][j] = msk ? -1e9f : s[i][j] * 0.125f;
        }

        // row max (across the 16 tx-lanes sharing a row)
        float mnew[4], corr[4];
#pragma unroll
        for (int i = 0; i < 4; i++) {
            float rm = fmaxf(fmaxf(s[i][0], s[i][1]), fmaxf(s[i][2], s[i][3]));
            rm = fmaxf(rm, __shfl_xor_sync(0xffffffffu, rm, 1));
            rm = fmaxf(rm, __shfl_xor_sync(0xffffffffu, rm, 2));
            rm = fmaxf(rm, __shfl_xor_sync(0xffffffffu, rm, 4));
            rm = fmaxf(rm, __shfl_xor_sync(0xffffffffu, rm, 8));
            mnew[i] = fmaxf(m_i[i], rm);
            corr[i] = expf(m_i[i] - mnew[i]);
            m_i[i] = mnew[i];
        }

        // p = exp(s - mnew), row sums, rescale o, update l
        float p[4][4];
#pragma unroll
        for (int i = 0; i < 4; i++) {
            float rs = 0.f;
#pragma unroll
            for (int j = 0; j < 4; j++) {
                p[i][j] = expf(s[i][j] - mnew[i]);
                rs += p[i][j];
            }
            rs += __shfl_xor_sync(0xffffffffu, rs, 1);
            rs += __shfl_xor_sync(0xffffffffu, rs, 2);
            rs += __shfl_xor_sync(0xffffffffu, rs, 4);
            rs += __shfl_xor_sync(0xffffffffu, rs, 8);
            l_i[i] = l_i[i] * corr[i] + rs;
#pragma unroll
            for (int j = 0; j < 4; j++) o[i][j] *= corr[i];
        }

        __syncthreads();  // all threads done reading KtP as K

        // write P row-major into KtP
#pragma unroll
        for (int i = 0; i < 4; i++) {
            float4 pv = make_float4(p[i][0], p[i][1], p[i][2], p[i][3]);
            *(float4*)&KtP[(ty * 4 + i) * 64 + tx * 4] = pv;
        }
        __syncthreads();

        // o += P @ V
#pragma unroll 4
        for (int kk = 0; kk < 64; kk++) {
            float a0 = KtP[(ty * 4 + 0) * 64 + kk];
            float a1 = KtP[(ty * 4 + 1) * 64 + kk];
            float a2 = KtP[(ty * 4 + 2) * 64 + kk];
            float a3 = KtP[(ty * 4 + 3) * 64 + kk];
            float4 bv = *(const float4*)&Vs[kk * 64 + tx * 4];
            float bb[4] = {bv.x, bv.y, bv.z, bv.w};
            float aa[4] = {a0, a1, a2, a3};
#pragma unroll
            for (int i = 0; i < 4; i++)
#pragma unroll
                for (int j = 0; j < 4; j++) o[i][j] = fmaf(aa[i], bb[j], o[i][j]);
        }
    }

    // finalize and write ctx in [tok][D] layout (head-major inner already correct)
#pragma unroll
    for (int i = 0; i < 4; i++) {
        const float inv = 1.f / l_i[i];
        float4 ov = make_float4(o[i][0] * inv, o[i][1] * inv, o[i][2] * inv, o[i][3] * inv);
        *(float4*)(ctx + base + (size_t)(q0 + ty * 4 + i) * D_ + tx * 4) = ov;
    }
}

// ---------------------------------------------------------------------------
// LayerNorm over rows of 1024. One block per row, 256 threads, float4 each.
// ---------------------------------------------------------------------------
__global__ __launch_bounds__(256) void ln_kernel(
    const float* __restrict__ in, const float* __restrict__ g,
    const float* __restrict__ be, float* __restrict__ out)
{
    __shared__ float sred[8], ssred[8];
    __shared__ float muSh, rsSh;

    const int row = blockIdx.x;
    const int tid = threadIdx.x;
    const int lane = tid & 31;
    const int wid = tid >> 5;

    const float* p = in + (size_t)row * D_;
    float4 x = *(const float4*)(p + tid * 4);
    float s = x.x + x.y + x.z + x.w;
    float ss = x.x * x.x + x.y * x.y + x.z * x.z + x.w * x.w;

#pragma unroll
    for (int off = 16; off > 0; off >>= 1) {
        s += __shfl_xor_sync(0xffffffffu, s, off);
        ss += __shfl_xor_sync(0xffffffffu, ss, off);
    }
    if (lane == 0) { sred[wid] = s; ssred[wid] = ss; }
    __syncthreads();
    if (wid == 0) {
        float s2 = (lane < 8) ? sred[lane] : 0.f;
        float ss2 = (lane < 8) ? ssred[lane] : 0.f;
#pragma unroll
        for (int off = 4; off > 0; off >>= 1) {
            s2 += __shfl_xor_sync(0xffffffffu, s2, off);
            ss2 += __shfl_xor_sync(0xffffffffu, ss2, off);
        }
        if (lane == 0) {
            const float mu = s2 * (1.f / D_);
            const float var = ss2 * (1.f / D_) - mu * mu;
            muSh = mu;
            rsSh = rsqrtf(var + 1e-6f);
        }
    }
    __syncthreads();

    const float mu = muSh, rs = rsSh;
    float4 gg = *(const float4*)(g + tid * 4);
    float4 bb = *(const float4*)(be + tid * 4);
    float4 y;
    y.x = (x.x - mu) * rs * gg.x + bb.x;
    y.y = (x.y - mu) * rs * gg.y + bb.y;
    y.z = (x.z - mu) * rs * gg.z + bb.z;
    y.w = (x.w - mu) * rs * gg.w + bb.w;
    *(float4*)(out + (size_t)row * D_ + tid * 4) = y;
}

// ---------------------------------------------------------------------------
// Launch: QKV gemms -> flash attention -> proj+residual -> LN1 ->
//         FFN1(relu) -> FFN2+residual -> LN2
// ---------------------------------------------------------------------------
extern "C" void kernel_launch(void* const* d_in, const int* in_sizes, int n_in,
                              void* d_out, int out_size)
{
    const float* x   = (const float*)d_in[0];
    const unsigned char* mask = (const unsigned char*)d_in[1];
    const float* wq = (const float*)d_in[2];
    const float* bq = (const float*)d_in[3];
    const float* wk = (const float*)d_in[4];
    const float* bk = (const float*)d_in[5];
    const float* wv = (const float*)d_in[6];
    const float* bv = (const float*)d_in[7];
    const float* wm = (const float*)d_in[8];
    const float* bm = (const float*)d_in[9];
    const float* w1 = (const float*)d_in[10];
    const float* b1 = (const float*)d_in[11];
    const float* w2 = (const float*)d_in[12];
    const float* b2 = (const float*)d_in[13];
    const float* g1  = (const float*)d_in[14];
    const float* be1 = (const float*)d_in[15];
    const float* g2  = (const float*)d_in[16];
    const float* be2 = (const float*)d_in[17];
    float* out = (float*)d_out;

    float *q, *k, *v, *ctx, *x1, *hb;
    cudaGetSymbolAddress((void**)&q, g_q);
    cudaGetSymbolAddress((void**)&k, g_k);
    cudaGetSymbolAddress((void**)&v, g_v);
    cudaGetSymbolAddress((void**)&ctx, g_ctx);
    cudaGetSymbolAddress((void**)&x1, g_x1);
    cudaGetSymbolAddress((void**)&hb, g_hb);

    const dim3 blk(256);
    const dim3 gD(D_ / GBN, NTOK / GBM);     // (8, 64)
    const dim3 gFF(FF_ / GBN, NTOK / GBM);   // (32, 64)

    // QKV projections
    sgemm_kernel<0><<<gD, blk>>>(x, wq, bq, nullptr, q, NTOK, D_, D_);
    sgemm_kernel<0><<<gD, blk>>>(x, wk, bk, nullptr, k, NTOK, D_, D_);
    sgemm_kernel<0><<<gD, blk>>>(x, wv, bv, nullptr, v, NTOK, D_, D_);

    // Flash attention -> ctx
    flash_kernel<<<dim3(S_ / 64, B_ * H_), blk>>>(q, k, v, mask, ctx);

    // atted = ctx @ wm + bm; y1 = x + atted  (reuse g_k)
    sgemm_kernel<2><<<gD, blk>>>(ctx, wm, bm, x, k, NTOK, D_, D_);
    ln_kernel<<<NTOK, blk>>>(k, g1, be1, x1);

    // FFN
    sgemm_kernel<1><<<gFF, blk>>>(x1, w1, b1, nullptr, hb, NTOK, FF_, D_);
    sgemm_kernel<2><<<gD, blk>>>(hb, w2, b2, x1, v, NTOK, D_, FF_);  // y2 in g_v
    ln_kernel<<<NTOK, blk>>>(v, g2, be2, out);
}

// round 2
// speedup vs baseline: 1.5302x; 1.5302x over previous
#include <cuda_runtime.h>
#include <math.h>
#include <stdint.h>

// Problem constants
#define B_   4
#define S_   2048
#define D_   1024
#define H_   16
#define DH_  64
#define FF_  4096
#define NTOK (B_ * S_)   // 8192

// ---------------------------------------------------------------------------
// Scratch buffers (device globals — no runtime allocation allowed)
// ---------------------------------------------------------------------------
__device__ float g_q[(size_t)NTOK * D_];
__device__ float g_k[(size_t)NTOK * D_];    // reused as (x + atted) after flash
__device__ float g_v[(size_t)NTOK * D_];    // reused as (x1 + ff) after flash
__device__ float g_ctx[(size_t)NTOK * D_];
__device__ float g_x1[(size_t)NTOK * D_];
__device__ float g_hb[(size_t)NTOK * FF_];

// ---------------------------------------------------------------------------
// tf32 helpers
// ---------------------------------------------------------------------------
__device__ __forceinline__ float f2tf32(float x) {
    uint32_t y;
    asm("cvt.rna.tf32.f32 %0, %1;" : "=r"(y) : "f"(x));
    return __uint_as_float(y);
}

__device__ __forceinline__ void mma_tf32(float* d, const uint32_t* a, const uint32_t* b) {
    asm volatile(
        "mma.sync.aligned.m16n8k8.row.col.f32.tf32.tf32.f32 "
        "{%0,%1,%2,%3}, {%4,%5,%6,%7}, {%8,%9}, {%0,%1,%2,%3};"
        : "+f"(d[0]), "+f"(d[1]), "+f"(d[2]), "+f"(d[3])
        : "r"(a[0]), "r"(a[1]), "r"(a[2]), "r"(a[3]), "r"(b[0]), "r"(b[1]));
}

// ---------------------------------------------------------------------------
// tf32 tensor-core GEMM: C[M,N] = A[M,K] @ W[K,N] + bias (+ relu / + residual)
// 128x128x32 CTA tile, 256 threads (8 warps, 2x4), warp tile 64x32.
// Smem double buffered (dynamic, 66,560 B).
// A fragment-permuted layout: As[ks(4)][mt(8)][lane(32)][reg(4)]  (16 KB/buf)
// B row-major padded:        Bs[k(32)][n(128)+4]                  (16.5 KB/buf)
// EPI: 0 = bias, 1 = bias+relu, 2 = bias+residual
// ---------------------------------------------------------------------------
#define TBM 128
#define TBN 128
#define TBK 32
#define BPAD 4
#define ASZ 4096           // floats per A buffer
#define BSZ (32 * (128 + BPAD))  // 4224 floats per B buffer
#define GEMM_SMEM_BYTES ((ASZ + BSZ) * 2 * 4)

template <int EPI>
__global__ __launch_bounds__(256, 1) void tgemm_kernel(
    const float* __restrict__ A, const float* __restrict__ W,
    const float* __restrict__ bias, const float* __restrict__ res,
    float* __restrict__ C, int M, int N, int K)
{
    extern __shared__ float smem[];
    float* As = smem;            // [2][ASZ]
    float* Bs = smem + 2 * ASZ;  // [2][BSZ]

    const int tid = threadIdx.x;
    const int lane = tid & 31;
    const int warp = tid >> 5;
    const int wm = warp >> 2;    // 0..1
    const int wn = warp & 3;     // 0..3
    const int bm = blockIdx.y * TBM;
    const int bn = blockIdx.x * TBN;

    // A loader mapping: thread loads 4 float4s
    const int arow = tid >> 3;            // 0..31 (+ i*32)
    const int acol = (tid & 7) << 2;      // 0..28
    const int a_ks = acol >> 3;
    const int a_creg = ((acol & 7) >> 2) << 1;  // 0 or 2
    // B loader mapping
    const int brow = tid >> 5;            // 0..7 (+ i*8)
    const int bcol = (tid & 31) << 2;

    const float* Ag = A + (size_t)(bm + arow) * K + acol;
    const float* Wg = W + (size_t)brow * N + bn + bcol;

    float acc[4][4][4];
#pragma unroll
    for (int i = 0; i < 4; i++)
#pragma unroll
        for (int j = 0; j < 4; j++)
#pragma unroll
            for (int r = 0; r < 4; r++) acc[i][j][r] = 0.f;

    const int NIT = K / TBK;
    float4 Ar[4], Br[4];

    // prologue: load tile 0
#pragma unroll
    for (int i = 0; i < 4; i++) {
        Ar[i] = *(const float4*)(Ag + (size_t)(i * 32) * K);
        Br[i] = *(const float4*)(Wg + (size_t)(i * 8) * N);
    }

    int buf = 0;
    // store tile 0 into smem[0]
    {
        float* as = As;
        float* bs = Bs;
#pragma unroll
        for (int i = 0; i < 4; i++) {
            const int row = arow + i * 32;
            const int mt = row >> 4;
            const int rb = ((row >> 3) & 1) + a_creg;
            const int base = (((a_ks * 8 + mt) * 32) + ((row & 7) << 2)) * 4 + rb;
            as[base +  0] = f2tf32(Ar[i].x);
            as[base +  4] = f2tf32(Ar[i].y);
            as[base +  8] = f2tf32(Ar[i].z);
            as[base + 12] = f2tf32(Ar[i].w);
            const int k = brow + i * 8;
            float4 bv = make_float4(f2tf32(Br[i].x), f2tf32(Br[i].y),
                                    f2tf32(Br[i].z), f2tf32(Br[i].w));
            *(float4*)(bs + k * (128 + BPAD) + bcol) = bv;
        }
    }
    __syncthreads();

    for (int it = 0; it < NIT; ++it) {
        if (it + 1 < NIT) {
            const int k0 = (it + 1) * TBK;
#pragma unroll
            for (int i = 0; i < 4; i++) {
                Ar[i] = *(const float4*)(Ag + (size_t)k0 + (size_t)(i * 32) * K);
                Br[i] = *(const float4*)(Wg + (size_t)(k0 + i * 8) * N);
            }
        }

        // compute from smem[buf]
        const float* as = As + buf * ASZ;
        const float* bs = Bs + buf * BSZ;
#pragma unroll
        for (int ks = 0; ks < 4; ks++) {
            uint32_t af[4][4];
#pragma unroll
            for (int i = 0; i < 4; i++) {
                const int mt = wm * 4 + i;
                float4 v = *(const float4*)(as + (((ks * 8 + mt) * 32) + lane) * 4);
                af[i][0] = __float_as_uint(v.x);
                af[i][1] = __float_as_uint(v.y);
                af[i][2] = __float_as_uint(v.z);
                af[i][3] = __float_as_uint(v.w);
            }
            uint32_t bf[4][2];
#pragma unroll
            for (int j = 0; j < 4; j++) {
                const int n = wn * 32 + j * 8 + (lane >> 2);
                const int k = ks * 8 + (lane & 3);
                bf[j][0] = __float_as_uint(bs[k * (128 + BPAD) + n]);
                bf[j][1] = __float_as_uint(bs[(k + 4) * (128 + BPAD) + n]);
            }
#pragma unroll
            for (int i = 0; i < 4; i++)
#pragma unroll
                for (int j = 0; j < 4; j++)
                    mma_tf32(acc[i][j], af[i], bf[j]);
        }

        if (it + 1 < NIT) {
            float* asn = As + (buf ^ 1) * ASZ;
            float* bsn = Bs + (buf ^ 1) * BSZ;
#pragma unroll
            for (int i = 0; i < 4; i++) {
                const int row = arow + i * 32;
                const int mt = row >> 4;
                const int rb = ((row >> 3) & 1) + a_creg;
                const int base = (((a_ks * 8 + mt) * 32) + ((row & 7) << 2)) * 4 + rb;
                asn[base +  0] = f2tf32(Ar[i].x);
                asn[base +  4] = f2tf32(Ar[i].y);
                asn[base +  8] = f2tf32(Ar[i].z);
                asn[base + 12] = f2tf32(Ar[i].w);
                const int k = brow + i * 8;
                float4 bv = make_float4(f2tf32(Br[i].x), f2tf32(Br[i].y),
                                        f2tf32(Br[i].z), f2tf32(Br[i].w));
                *(float4*)(bsn + k * (128 + BPAD) + bcol) = bv;
            }
            __syncthreads();
            buf ^= 1;
        }
    }

    // Epilogue: each acc tile -> rows (r0, r0+8), cols (col, col+1)
#pragma unroll
    for (int i = 0; i < 4; i++) {
        const int r0 = bm + wm * 64 + i * 16 + (lane >> 2);
#pragma unroll
        for (int j = 0; j < 4; j++) {
            const int col = bn + wn * 32 + j * 8 + (lane & 3) * 2;
            float2 bi = *(const float2*)(bias + col);
            float o00 = acc[i][j][0] + bi.x;
            float o01 = acc[i][j][1] + bi.y;
            float o10 = acc[i][j][2] + bi.x;
            float o11 = acc[i][j][3] + bi.y;
            if (EPI == 1) {
                o00 = fmaxf(o00, 0.f); o01 = fmaxf(o01, 0.f);
                o10 = fmaxf(o10, 0.f); o11 = fmaxf(o11, 0.f);
            }
            if (EPI == 2) {
                float2 r0v = *(const float2*)(res + (size_t)r0 * N + col);
                float2 r1v = *(const float2*)(res + (size_t)(r0 + 8) * N + col);
                o00 += r0v.x; o01 += r0v.y;
                o10 += r1v.x; o11 += r1v.y;
            }
            *(float2*)(C + (size_t)r0 * N + col) = make_float2(o00, o01);
            *(float2*)(C + (size_t)(r0 + 8) * N + col) = make_float2(o10, o11);
        }
    }
}

// ---------------------------------------------------------------------------
// Flash attention (unchanged from round 1): one CTA per (b,h,64-query tile).
// ---------------------------------------------------------------------------
__global__ __launch_bounds__(256) void flash_kernel(
    const float* __restrict__ q, const float* __restrict__ k,
    const float* __restrict__ v, const unsigned char* __restrict__ mask,
    float* __restrict__ ctx)
{
    __shared__ float Qt[64 * 64];
    __shared__ float KtP[64 * 64];
    __shared__ float Vs[64 * 64];

    const int tid = threadIdx.x;
    const int tx = tid & 15;
    const int ty = tid >> 4;
    const int bh = blockIdx.y;
    const int b  = bh >> 4;
    const int h  = bh & 15;
    const int q0 = blockIdx.x * 64;
    const size_t base = (size_t)b * S_ * D_ + (size_t)h * DH_;
    const unsigned char* mrow = mask + (size_t)b * S_;

    for (int s4 = tid; s4 < 64 * 16; s4 += 256) {
        const int tok = s4 >> 4;
        const int d = (s4 & 15) << 2;
        float4 qv = *(const float4*)(q + base + (size_t)(q0 + tok) * D_ + d);
        Qt[(d + 0) * 64 + tok] = qv.x;
        Qt[(d + 1) * 64 + tok] = qv.y;
        Qt[(d + 2) * 64 + tok] = qv.z;
        Qt[(d + 3) * 64 + tok] = qv.w;
    }

    float o[4][4];
    float m_i[4], l_i[4];
#pragma unroll
    for (int i = 0; i < 4; i++) {
        m_i[i] = -1e30f;
        l_i[i] = 0.f;
#pragma unroll
        for (int j = 0; j < 4; j++) o[i][j] = 0.f;
    }

    for (int kt = 0; kt < S_; kt += 64) {
        __syncthreads();

        for (int s4 = tid; s4 < 64 * 16; s4 += 256) {
            const int tok = s4 >> 4;
            const int d = (s4 & 15) << 2;
            float4 kv = *(const float4*)(k + base + (size_t)(kt + tok) * D_ + d);
            KtP[(d + 0) * 64 + tok] = kv.x;
            KtP[(d + 1) * 64 + tok] = kv.y;
            KtP[(d + 2) * 64 + tok] = kv.z;
            KtP[(d + 3) * 64 + tok] = kv.w;
            float4 vv = *(const float4*)(v + base + (size_t)(kt + tok) * D_ + d);
            *(float4*)&Vs[tok * 64 + d] = vv;
        }
        __syncthreads();

        float s[4][4];
#pragma unroll
        for (int i = 0; i < 4; i++)
#pragma unroll
            for (int j = 0; j < 4; j++) s[i][j] = 0.f;

#pragma unroll 4
        for (int d = 0; d < 64; d++) {
            float4 aq = *(const float4*)&Qt[d * 64 + ty * 4];
            float4 bk4 = *(const float4*)&KtP[d * 64 + tx * 4];
            float a[4] = {aq.x, aq.y, aq.z, aq.w};
            float bb[4] = {bk4.x, bk4.y, bk4.z, bk4.w};
#pragma unroll
            for (int i = 0; i < 4; i++)
#pragma unroll
                for (int j = 0; j < 4; j++) s[i][j] = fmaf(a[i], bb[j], s[i][j]);
        }

#pragma unroll
        for (int j = 0; j < 4; j++) {
            const bool msk = mrow[kt + tx * 4 + j] != 0;
#pragma unroll
            for (int i = 0; i < 4; i++)
                s[i][j] = msk ? -1e9f : s[i][j] * 0.125f;
        }

        float mnew[4], corr[4];
#pragma unroll
        for (int i = 0; i < 4; i++) {
            float rm = fmaxf(fmaxf(s[i][0], s[i][1]), fmaxf(s[i][2], s[i][3]));
            rm = fmaxf(rm, __shfl_xor_sync(0xffffffffu, rm, 1));
            rm = fmaxf(rm, __shfl_xor_sync(0xffffffffu, rm, 2));
            rm = fmaxf(rm, __shfl_xor_sync(0xffffffffu, rm, 4));
            rm = fmaxf(rm, __shfl_xor_sync(0xffffffffu, rm, 8));
            mnew[i] = fmaxf(m_i[i], rm);
            corr[i] = expf(m_i[i] - mnew[i]);
            m_i[i] = mnew[i];
        }

        float p[4][4];
#pragma unroll
        for (int i = 0; i < 4; i++) {
            float rs = 0.f;
#pragma unroll
            for (int j = 0; j < 4; j++) {
                p[i][j] = expf(s[i][j] - mnew[i]);
                rs += p[i][j];
            }
            rs += __shfl_xor_sync(0xffffffffu, rs, 1);
            rs += __shfl_xor_sync(0xffffffffu, rs, 2);
            rs += __shfl_xor_sync(0xffffffffu, rs, 4);
            rs += __shfl_xor_sync(0xffffffffu, rs, 8);
            l_i[i] = l_i[i] * corr[i] + rs;
#pragma unroll
            for (int j = 0; j < 4; j++) o[i][j] *= corr[i];
        }

        __syncthreads();

#pragma unroll
        for (int i = 0; i < 4; i++) {
            float4 pv = make_float4(p[i][0], p[i][1], p[i][2], p[i][3]);
            *(float4*)&KtP[(ty * 4 + i) * 64 + tx * 4] = pv;
        }
        __syncthreads();

#pragma unroll 4
        for (int kk = 0; kk < 64; kk++) {
            float a0 = KtP[(ty * 4 + 0) * 64 + kk];
            float a1 = KtP[(ty * 4 + 1) * 64 + kk];
            float a2 = KtP[(ty * 4 + 2) * 64 + kk];
            float a3 = KtP[(ty * 4 + 3) * 64 + kk];
            float4 bv = *(const float4*)&Vs[kk * 64 + tx * 4];
            float bb[4] = {bv.x, bv.y, bv.z, bv.w};
            float aa[4] = {a0, a1, a2, a3};
#pragma unroll
            for (int i = 0; i < 4; i++)
#pragma unroll
                for (int j = 0; j < 4; j++) o[i][j] = fmaf(aa[i], bb[j], o[i][j]);
        }
    }

#pragma unroll
    for (int i = 0; i < 4; i++) {
        const float inv = 1.f / l_i[i];
        float4 ov = make_float4(o[i][0] * inv, o[i][1] * inv, o[i][2] * inv, o[i][3] * inv);
        *(float4*)(ctx + base + (size_t)(q0 + ty * 4 + i) * D_ + tx * 4) = ov;
    }
}

// ---------------------------------------------------------------------------
// LayerNorm (unchanged)
// ---------------------------------------------------------------------------
__global__ __launch_bounds__(256) void ln_kernel(
    const float* __restrict__ in, const float* __restrict__ g,
    const float* __restrict__ be, float* __restrict__ out)
{
    __shared__ float sred[8], ssred[8];
    __shared__ float muSh, rsSh;

    const int row = blockIdx.x;
    const int tid = threadIdx.x;
    const int lane = tid & 31;
    const int wid = tid >> 5;

    const float* p = in + (size_t)row * D_;
    float4 x = *(const float4*)(p + tid * 4);
    float s = x.x + x.y + x.z + x.w;
    float ss = x.x * x.x + x.y * x.y + x.z * x.z + x.w * x.w;

#pragma unroll
    for (int off = 16; off > 0; off >>= 1) {
        s += __shfl_xor_sync(0xffffffffu, s, off);
        ss += __shfl_xor_sync(0xffffffffu, ss, off);
    }
    if (lane == 0) { sred[wid] = s; ssred[wid] = ss; }
    __syncthreads();
    if (wid == 0) {
        float s2 = (lane < 8) ? sred[lane] : 0.f;
        float ss2 = (lane < 8) ? ssred[lane] : 0.f;
#pragma unroll
        for (int off = 4; off > 0; off >>= 1) {
            s2 += __shfl_xor_sync(0xffffffffu, s2, off);
            ss2 += __shfl_xor_sync(0xffffffffu, ss2, off);
        }
        if (lane == 0) {
            const float mu = s2 * (1.f / D_);
            const float var = ss2 * (1.f / D_) - mu * mu;
            muSh = mu;
            rsSh = rsqrtf(var + 1e-6f);
        }
    }
    __syncthreads();

    const float mu = muSh, rs = rsSh;
    float4 gg = *(const float4*)(g + tid * 4);
    float4 bb = *(const float4*)(be + tid * 4);
    float4 y;
    y.x = (x.x - mu) * rs * gg.x + bb.x;
    y.y = (x.y - mu) * rs * gg.y + bb.y;
    y.z = (x.z - mu) * rs * gg.z + bb.z;
    y.w = (x.w - mu) * rs * gg.w + bb.w;
    *(float4*)(out + (size_t)row * D_ + tid * 4) = y;
}

// ---------------------------------------------------------------------------
// Launch
// ---------------------------------------------------------------------------
extern "C" void kernel_launch(void* const* d_in, const int* in_sizes, int n_in,
                              void* d_out, int out_size)
{
    const float* x   = (const float*)d_in[0];
    const unsigned char* mask = (const unsigned char*)d_in[1];
    const float* wq = (const float*)d_in[2];
    const float* bq = (const float*)d_in[3];
    const float* wk = (const float*)d_in[4];
    const float* bk = (const float*)d_in[5];
    const float* wv = (const float*)d_in[6];
    const float* bv = (const float*)d_in[7];
    const float* wm = (const float*)d_in[8];
    const float* bm = (const float*)d_in[9];
    const float* w1 = (const float*)d_in[10];
    const float* b1 = (const float*)d_in[11];
    const float* w2 = (const float*)d_in[12];
    const float* b2 = (const float*)d_in[13];
    const float* g1  = (const float*)d_in[14];
    const float* be1 = (const float*)d_in[15];
    const float* g2  = (const float*)d_in[16];
    const float* be2 = (const float*)d_in[17];
    float* out = (float*)d_out;

    float *q, *k, *v, *ctx, *x1, *hb;
    cudaGetSymbolAddress((void**)&q, g_q);
    cudaGetSymbolAddress((void**)&k, g_k);
    cudaGetSymbolAddress((void**)&v, g_v);
    cudaGetSymbolAddress((void**)&ctx, g_ctx);
    cudaGetSymbolAddress((void**)&x1, g_x1);
    cudaGetSymbolAddress((void**)&hb, g_hb);

    static bool attr_set = false;
    if (!attr_set) {
        cudaFuncSetAttribute(tgemm_kernel<0>, cudaFuncAttributeMaxDynamicSharedMemorySize, GEMM_SMEM_BYTES);
        cudaFuncSetAttribute(tgemm_kernel<1>, cudaFuncAttributeMaxDynamicSharedMemorySize, GEMM_SMEM_BYTES);
        cudaFuncSetAttribute(tgemm_kernel<2>, cudaFuncAttributeMaxDynamicSharedMemorySize, GEMM_SMEM_BYTES);
        attr_set = true;
    }

    const dim3 blk(256);
    const dim3 gD(D_ / TBN, NTOK / TBM);     // (8, 64)
    const dim3 gFF(FF_ / TBN, NTOK / TBM);   // (32, 64)

    // QKV projections
    tgemm_kernel<0><<<gD, blk, GEMM_SMEM_BYTES>>>(x, wq, bq, nullptr, q, NTOK, D_, D_);
    tgemm_kernel<0><<<gD, blk, GEMM_SMEM_BYTES>>>(x, wk, bk, nullptr, k, NTOK, D_, D_);
    tgemm_kernel<0><<<gD, blk, GEMM_SMEM_BYTES>>>(x, wv, bv, nullptr, v, NTOK, D_, D_);

    // Flash attention -> ctx
    flash_kernel<<<dim3(S_ / 64, B_ * H_), blk>>>(q, k, v, mask, ctx);

    // atted = ctx @ wm + bm; y1 = x + atted  (into g_k)
    tgemm_kernel<2><<<gD, blk, GEMM_SMEM_BYTES>>>(ctx, wm, bm, x, k, NTOK, D_, D_);
    ln_kernel<<<NTOK, blk>>>(k, g1, be1, x1);

    // FFN
    tgemm_kernel<1><<<gFF, blk, GEMM_SMEM_BYTES>>>(x1, w1, b1, nullptr, hb, NTOK, FF_, D_);
    tgemm_kernel<2><<<gD, blk, GEMM_SMEM_BYTES>>>(hb, w2, b2, x1, v, NTOK, D_, FF_);
    ln_kernel<<<NTOK, blk>>>(v, g2, be2, out);
}

// round 3
// speedup vs baseline: 2.0328x; 1.3284x over previous
#include <cuda_runtime.h>
#include <math.h>
#include <stdint.h>

// Problem constants
#define B_   4
#define S_   2048
#define D_   1024
#define H_   16
#define DH_  64
#define FF_  4096
#define NTOK (B_ * S_)   // 8192

// ---------------------------------------------------------------------------
// Scratch buffers (device globals — no runtime allocation allowed)
// ---------------------------------------------------------------------------
__device__ float g_q[(size_t)NTOK * D_];
__device__ float g_k[(size_t)NTOK * D_];
__device__ float g_v[(size_t)NTOK * D_];
__device__ float g_ctx[(size_t)NTOK * D_];
__device__ float g_x1[(size_t)NTOK * D_];
__device__ float g_hb[(size_t)NTOK * FF_];

// ---------------------------------------------------------------------------
// tf32 helpers
// ---------------------------------------------------------------------------
__device__ __forceinline__ float f2tf32(float x) {
    uint32_t y;
    asm("cvt.rna.tf32.f32 %0, %1;" : "=r"(y) : "f"(x));
    return __uint_as_float(y);
}

__device__ __forceinline__ void mma_tf32(float* d, const uint32_t* a, const uint32_t* b) {
    asm volatile(
        "mma.sync.aligned.m16n8k8.row.col.f32.tf32.tf32.f32 "
        "{%0,%1,%2,%3}, {%4,%5,%6,%7}, {%8,%9}, {%0,%1,%2,%3};"
        : "+f"(d[0]), "+f"(d[1]), "+f"(d[2]), "+f"(d[3])
        : "r"(a[0]), "r"(a[1]), "r"(a[2]), "r"(a[3]), "r"(b[0]), "r"(b[1]));
}

// ---------------------------------------------------------------------------
// tf32 tensor-core GEMM (unchanged from round 2)
// ---------------------------------------------------------------------------
#define TBM 128
#define TBN 128
#define TBK 32
#define BPAD 4
#define ASZ 4096
#define BSZ (32 * (128 + BPAD))
#define GEMM_SMEM_BYTES ((ASZ + BSZ) * 2 * 4)

template <int EPI>
__global__ __launch_bounds__(256, 1) void tgemm_kernel(
    const float* __restrict__ A, const float* __restrict__ W,
    const float* __restrict__ bias, const float* __restrict__ res,
    float* __restrict__ C, int M, int N, int K)
{
    extern __shared__ float smem[];
    float* As = smem;
    float* Bs = smem + 2 * ASZ;

    const int tid = threadIdx.x;
    const int lane = tid & 31;
    const int warp = tid >> 5;
    const int wm = warp >> 2;
    const int wn = warp & 3;
    const int bm = blockIdx.y * TBM;
    const int bn = blockIdx.x * TBN;

    const int arow = tid >> 3;
    const int acol = (tid & 7) << 2;
    const int a_ks = acol >> 3;
    const int a_creg = ((acol & 7) >> 2) << 1;
    const int brow = tid >> 5;
    const int bcol = (tid & 31) << 2;

    const float* Ag = A + (size_t)(bm + arow) * K + acol;
    const float* Wg = W + (size_t)brow * N + bn + bcol;

    float acc[4][4][4];
#pragma unroll
    for (int i = 0; i < 4; i++)
#pragma unroll
        for (int j = 0; j < 4; j++)
#pragma unroll
            for (int r = 0; r < 4; r++) acc[i][j][r] = 0.f;

    const int NIT = K / TBK;
    float4 Ar[4], Br[4];

#pragma unroll
    for (int i = 0; i < 4; i++) {
        Ar[i] = *(const float4*)(Ag + (size_t)(i * 32) * K);
        Br[i] = *(const float4*)(Wg + (size_t)(i * 8) * N);
    }

    int buf = 0;
    {
        float* as = As;
        float* bs = Bs;
#pragma unroll
        for (int i = 0; i < 4; i++) {
            const int row = arow + i * 32;
            const int mt = row >> 4;
            const int rb = ((row >> 3) & 1) + a_creg;
            const int base = (((a_ks * 8 + mt) * 32) + ((row & 7) << 2)) * 4 + rb;
            as[base +  0] = f2tf32(Ar[i].x);
            as[base +  4] = f2tf32(Ar[i].y);
            as[base +  8] = f2tf32(Ar[i].z);
            as[base + 12] = f2tf32(Ar[i].w);
            const int k = brow + i * 8;
            float4 bv = make_float4(f2tf32(Br[i].x), f2tf32(Br[i].y),
                                    f2tf32(Br[i].z), f2tf32(Br[i].w));
            *(float4*)(bs + k * (128 + BPAD) + bcol) = bv;
        }
    }
    __syncthreads();

    for (int it = 0; it < NIT; ++it) {
        if (it + 1 < NIT) {
            const int k0 = (it + 1) * TBK;
#pragma unroll
            for (int i = 0; i < 4; i++) {
                Ar[i] = *(const float4*)(Ag + (size_t)k0 + (size_t)(i * 32) * K);
                Br[i] = *(const float4*)(Wg + (size_t)(k0 + i * 8) * N);
            }
        }

        const float* as = As + buf * ASZ;
        const float* bs = Bs + buf * BSZ;
#pragma unroll
        for (int ks = 0; ks < 4; ks++) {
            uint32_t af[4][4];
#pragma unroll
            for (int i = 0; i < 4; i++) {
                const int mt = wm * 4 + i;
                float4 v = *(const float4*)(as + (((ks * 8 + mt) * 32) + lane) * 4);
                af[i][0] = __float_as_uint(v.x);
                af[i][1] = __float_as_uint(v.y);
                af[i][2] = __float_as_uint(v.z);
                af[i][3] = __float_as_uint(v.w);
            }
            uint32_t bf[4][2];
#pragma unroll
            for (int j = 0; j < 4; j++) {
                const int n = wn * 32 + j * 8 + (lane >> 2);
                const int k = ks * 8 + (lane & 3);
                bf[j][0] = __float_as_uint(bs[k * (128 + BPAD) + n]);
                bf[j][1] = __float_as_uint(bs[(k + 4) * (128 + BPAD) + n]);
            }
#pragma unroll
            for (int i = 0; i < 4; i++)
#pragma unroll
                for (int j = 0; j < 4; j++)
                    mma_tf32(acc[i][j], af[i], bf[j]);
        }

        if (it + 1 < NIT) {
            float* asn = As + (buf ^ 1) * ASZ;
            float* bsn = Bs + (buf ^ 1) * BSZ;
#pragma unroll
            for (int i = 0; i < 4; i++) {
                const int row = arow + i * 32;
                const int mt = row >> 4;
                const int rb = ((row >> 3) & 1) + a_creg;
                const int base = (((a_ks * 8 + mt) * 32) + ((row & 7) << 2)) * 4 + rb;
                asn[base +  0] = f2tf32(Ar[i].x);
                asn[base +  4] = f2tf32(Ar[i].y);
                asn[base +  8] = f2tf32(Ar[i].z);
                asn[base + 12] = f2tf32(Ar[i].w);
                const int k = brow + i * 8;
                float4 bv = make_float4(f2tf32(Br[i].x), f2tf32(Br[i].y),
                                        f2tf32(Br[i].z), f2tf32(Br[i].w));
                *(float4*)(bsn + k * (128 + BPAD) + bcol) = bv;
            }
            __syncthreads();
            buf ^= 1;
        }
    }

#pragma unroll
    for (int i = 0; i < 4; i++) {
        const int r0 = bm + wm * 64 + i * 16 + (lane >> 2);
#pragma unroll
        for (int j = 0; j < 4; j++) {
            const int col = bn + wn * 32 + j * 8 + (lane & 3) * 2;
            float2 bi = *(const float2*)(bias + col);
            float o00 = acc[i][j][0] + bi.x;
            float o01 = acc[i][j][1] + bi.y;
            float o10 = acc[i][j][2] + bi.x;
            float o11 = acc[i][j][3] + bi.y;
            if (EPI == 1) {
                o00 = fmaxf(o00, 0.f); o01 = fmaxf(o01, 0.f);
                o10 = fmaxf(o10, 0.f); o11 = fmaxf(o11, 0.f);
            }
            if (EPI == 2) {
                float2 r0v = *(const float2*)(res + (size_t)r0 * N + col);
                float2 r1v = *(const float2*)(res + (size_t)(r0 + 8) * N + col);
                o00 += r0v.x; o01 += r0v.y;
                o10 += r1v.x; o11 += r1v.y;
            }
            *(float2*)(C + (size_t)r0 * N + col) = make_float2(o00, o01);
            *(float2*)(C + (size_t)(r0 + 8) * N + col) = make_float2(o10, o11);
        }
    }
}

// ---------------------------------------------------------------------------
// Tensor-core flash attention (tf32 mma.sync).
// CTA: 128 queries x (b,h). 8 warps, each owns 16 query rows.
// Key tiles of 64 streamed through smem. Q lives in registers (A frags).
// Smem: Ks[64][68] + Vs[64][72] + Ps[128][68]  = 70,656 B dynamic.
// Ps doubles as Q staging; each warp's P region == its own Q rows.
// ---------------------------------------------------------------------------
#define FBQ 128
#define FBK 64
#define KS_STRIDE 68
#define VS_STRIDE 72
#define PS_STRIDE 68
#define FLASH_SMEM_BYTES ((64 * KS_STRIDE + 64 * VS_STRIDE + 128 * PS_STRIDE) * 4)

__global__ __launch_bounds__(256, 1) void flash_tc_kernel(
    const float* __restrict__ q, const float* __restrict__ k,
    const float* __restrict__ v, const unsigned char* __restrict__ mask,
    float* __restrict__ ctx)
{
    extern __shared__ float fsm[];
    float* Ks = fsm;                                    // [64][68]
    float* Vs = fsm + 64 * KS_STRIDE;                   // [64][72]
    float* Ps = fsm + 64 * KS_STRIDE + 64 * VS_STRIDE;  // [128][68]

    const int tid = threadIdx.x;
    const int lane = tid & 31;
    const int warp = tid >> 5;
    const int bh = blockIdx.y;
    const int b = bh >> 4;
    const int h = bh & 15;
    const int q0 = blockIdx.x * FBQ;
    const size_t base = (size_t)b * S_ * D_ + (size_t)h * DH_;
    const unsigned char* mrow = mask + (size_t)b * S_;

    const int r0 = lane >> 2;   // 0..7
    const int c0 = lane & 3;    // 0..3

    // Stage Q tile into Ps (tf32), coalesced
    for (int s4 = tid; s4 < FBQ * 16; s4 += 256) {
        const int row = s4 >> 4;
        const int cc = (s4 & 15) << 2;
        float4 qv = *(const float4*)(q + base + (size_t)(q0 + row) * D_ + cc);
        *(float4*)(Ps + row * PS_STRIDE + cc) =
            make_float4(f2tf32(qv.x), f2tf32(qv.y), f2tf32(qv.z), f2tf32(qv.w));
    }
    __syncthreads();

    // Extract Q A-fragments (warp reads only its own 16 rows)
    uint32_t qf[8][4];
    {
        const float* pw = Ps + (warp * 16) * PS_STRIDE;
#pragma unroll
        for (int ks = 0; ks < 8; ks++) {
            qf[ks][0] = __float_as_uint(pw[r0 * PS_STRIDE + ks * 8 + c0]);
            qf[ks][1] = __float_as_uint(pw[(r0 + 8) * PS_STRIDE + ks * 8 + c0]);
            qf[ks][2] = __float_as_uint(pw[r0 * PS_STRIDE + ks * 8 + c0 + 4]);
            qf[ks][3] = __float_as_uint(pw[(r0 + 8) * PS_STRIDE + ks * 8 + c0 + 4]);
        }
    }
    __syncwarp();

    float oa[8][4];
    float mx0 = -1e30f, mx1 = -1e30f, l0 = 0.f, l1 = 0.f;
#pragma unroll
    for (int j = 0; j < 8; j++)
#pragma unroll
        for (int r = 0; r < 4; r++) oa[j][r] = 0.f;

    float* Pw = Ps + (warp * 16) * PS_STRIDE;  // warp-private P region

    for (int kt = 0; kt < S_; kt += FBK) {
        __syncthreads();  // everyone done with previous Ks/Vs

        // Load K/V tiles (tf32 at store)
        for (int s4 = tid; s4 < FBK * 16; s4 += 256) {
            const int row = s4 >> 4;
            const int cc = (s4 & 15) << 2;
            float4 kv = *(const float4*)(k + base + (size_t)(kt + row) * D_ + cc);
            *(float4*)(Ks + row * KS_STRIDE + cc) =
                make_float4(f2tf32(kv.x), f2tf32(kv.y), f2tf32(kv.z), f2tf32(kv.w));
            float4 vv = *(const float4*)(v + base + (size_t)(kt + row) * D_ + cc);
            *(float4*)(Vs + row * VS_STRIDE + cc) =
                make_float4(f2tf32(vv.x), f2tf32(vv.y), f2tf32(vv.z), f2tf32(vv.w));
        }
        __syncthreads();

        // ---- S = Q @ K^T : warp tile 16x64 ----
        float sa[8][4];
#pragma unroll
        for (int j = 0; j < 8; j++)
#pragma unroll
            for (int r = 0; r < 4; r++) sa[j][r] = 0.f;

#pragma unroll
        for (int ks = 0; ks < 8; ks++) {
            uint32_t bf[8][2];
#pragma unroll
            for (int j = 0; j < 8; j++) {
                bf[j][0] = __float_as_uint(Ks[(j * 8 + r0) * KS_STRIDE + ks * 8 + c0]);
                bf[j][1] = __float_as_uint(Ks[(j * 8 + r0) * KS_STRIDE + ks * 8 + c0 + 4]);
            }
#pragma unroll
            for (int j = 0; j < 8; j++) mma_tf32(sa[j], qf[ks], bf[j]);
        }

        // ---- scale + mask + row max ----
        float rm0 = -1e30f, rm1 = -1e30f;
#pragma unroll
        for (int j = 0; j < 8; j++) {
            const int col = kt + j * 8 + 2 * c0;
            const bool m0 = mrow[col] != 0;
            const bool m1 = mrow[col + 1] != 0;
            sa[j][0] = m0 ? -1e9f : sa[j][0] * 0.125f;
            sa[j][1] = m1 ? -1e9f : sa[j][1] * 0.125f;
            sa[j][2] = m0 ? -1e9f : sa[j][2] * 0.125f;
            sa[j][3] = m1 ? -1e9f : sa[j][3] * 0.125f;
            rm0 = fmaxf(rm0, fmaxf(sa[j][0], sa[j][1]));
            rm1 = fmaxf(rm1, fmaxf(sa[j][2], sa[j][3]));
        }
        rm0 = fmaxf(rm0, __shfl_xor_sync(0xffffffffu, rm0, 1));
        rm0 = fmaxf(rm0, __shfl_xor_sync(0xffffffffu, rm0, 2));
        rm1 = fmaxf(rm1, __shfl_xor_sync(0xffffffffu, rm1, 1));
        rm1 = fmaxf(rm1, __shfl_xor_sync(0xffffffffu, rm1, 2));

        const float mn0 = fmaxf(mx0, rm0);
        const float mn1 = fmaxf(mx1, rm1);
        const float corr0 = __expf(mx0 - mn0);
        const float corr1 = __expf(mx1 - mn1);
        mx0 = mn0; mx1 = mn1;

        // ---- p = exp(s - m), write P (tf32), rescale O ----
        float rs0 = 0.f, rs1 = 0.f;
#pragma unroll
        for (int j = 0; j < 8; j++) {
            const float p0 = __expf(sa[j][0] - mn0);
            const float p1 = __expf(sa[j][1] - mn0);
            const float p2 = __expf(sa[j][2] - mn1);
            const float p3 = __expf(sa[j][3] - mn1);
            rs0 += p0 + p1;
            rs1 += p2 + p3;
            *(float2*)(Pw + r0 * PS_STRIDE + j * 8 + 2 * c0) =
                make_float2(f2tf32(p0), f2tf32(p1));
            *(float2*)(Pw + (r0 + 8) * PS_STRIDE + j * 8 + 2 * c0) =
                make_float2(f2tf32(p2), f2tf32(p3));
            oa[j][0] *= corr0; oa[j][1] *= corr0;
            oa[j][2] *= corr1; oa[j][3] *= corr1;
        }
        rs0 += __shfl_xor_sync(0xffffffffu, rs0, 1);
        rs0 += __shfl_xor_sync(0xffffffffu, rs0, 2);
        rs1 += __shfl_xor_sync(0xffffffffu, rs1, 1);
        rs1 += __shfl_xor_sync(0xffffffffu, rs1, 2);
        l0 = l0 * corr0 + rs0;
        l1 = l1 * corr1 + rs1;

        __syncwarp();  // P visible within warp

        // ---- O += P @ V ----
#pragma unroll
        for (int ks = 0; ks < 8; ks++) {
            uint32_t pf[4];
            pf[0] = __float_as_uint(Pw[r0 * PS_STRIDE + ks * 8 + c0]);
            pf[1] = __float_as_uint(Pw[(r0 + 8) * PS_STRIDE + ks * 8 + c0]);
            pf[2] = __float_as_uint(Pw[r0 * PS_STRIDE + ks * 8 + c0 + 4]);
            pf[3] = __float_as_uint(Pw[(r0 + 8) * PS_STRIDE + ks * 8 + c0 + 4]);
#pragma unroll
            for (int j = 0; j < 8; j++) {
                uint32_t bf2[2];
                bf2[0] = __float_as_uint(Vs[(ks * 8 + c0) * VS_STRIDE + j * 8 + r0]);
                bf2[1] = __float_as_uint(Vs[(ks * 8 + c0 + 4) * VS_STRIDE + j * 8 + r0]);
                mma_tf32(oa[j], pf, bf2);
            }
        }
        __syncwarp();  // P reads done before next tile's P writes
    }

    // ---- finalize: O / l, write ctx ----
    const float inv0 = 1.f / l0;
    const float inv1 = 1.f / l1;
    const int row0 = q0 + warp * 16 + r0;
#pragma unroll
    for (int j = 0; j < 8; j++) {
        const int col = j * 8 + 2 * c0;
        *(float2*)(ctx + base + (size_t)row0 * D_ + col) =
            make_float2(oa[j][0] * inv0, oa[j][1] * inv0);
        *(float2*)(ctx + base + (size_t)(row0 + 8) * D_ + col) =
            make_float2(oa[j][2] * inv1, oa[j][3] * inv1);
    }
}

// ---------------------------------------------------------------------------
// LayerNorm (unchanged)
// ---------------------------------------------------------------------------
__global__ __launch_bounds__(256) void ln_kernel(
    const float* __restrict__ in, const float* __restrict__ g,
    const float* __restrict__ be, float* __restrict__ out)
{
    __shared__ float sred[8], ssred[8];
    __shared__ float muSh, rsSh;

    const int row = blockIdx.x;
    const int tid = threadIdx.x;
    const int lane = tid & 31;
    const int wid = tid >> 5;

    const float* p = in + (size_t)row * D_;
    float4 x = *(const float4*)(p + tid * 4);
    float s = x.x + x.y + x.z + x.w;
    float ss = x.x * x.x + x.y * x.y + x.z * x.z + x.w * x.w;

#pragma unroll
    for (int off = 16; off > 0; off >>= 1) {
        s += __shfl_xor_sync(0xffffffffu, s, off);
        ss += __shfl_xor_sync(0xffffffffu, ss, off);
    }
    if (lane == 0) { sred[wid] = s; ssred[wid] = ss; }
    __syncthreads();
    if (wid == 0) {
        float s2 = (lane < 8) ? sred[lane] : 0.f;
        float ss2 = (lane < 8) ? ssred[lane] : 0.f;
#pragma unroll
        for (int off = 4; off > 0; off >>= 1) {
            s2 += __shfl_xor_sync(0xffffffffu, s2, off);
            ss2 += __shfl_xor_sync(0xffffffffu, ss2, off);
        }
        if (lane == 0) {
            const float mu = s2 * (1.f / D_);
            const float var = ss2 * (1.f / D_) - mu * mu;
            muSh = mu;
            rsSh = rsqrtf(var + 1e-6f);
        }
    }
    __syncthreads();

    const float mu = muSh, rs = rsSh;
    float4 gg = *(const float4*)(g + tid * 4);
    float4 bb = *(const float4*)(be + tid * 4);
    float4 y;
    y.x = (x.x - mu) * rs * gg.x + bb.x;
    y.y = (x.y - mu) * rs * gg.y + bb.y;
    y.z = (x.z - mu) * rs * gg.z + bb.z;
    y.w = (x.w - mu) * rs * gg.w + bb.w;
    *(float4*)(out + (size_t)row * D_ + tid * 4) = y;
}

// ---------------------------------------------------------------------------
// Launch
// ---------------------------------------------------------------------------
extern "C" void kernel_launch(void* const* d_in, const int* in_sizes, int n_in,
                              void* d_out, int out_size)
{
    const float* x   = (const float*)d_in[0];
    const unsigned char* mask = (const unsigned char*)d_in[1];
    const float* wq = (const float*)d_in[2];
    const float* bq = (const float*)d_in[3];
    const float* wk = (const float*)d_in[4];
    const float* bk = (const float*)d_in[5];
    const float* wv = (const float*)d_in[6];
    const float* bv = (const float*)d_in[7];
    const float* wm = (const float*)d_in[8];
    const float* bm = (const float*)d_in[9];
    const float* w1 = (const float*)d_in[10];
    const float* b1 = (const float*)d_in[11];
    const float* w2 = (const float*)d_in[12];
    const float* b2 = (const float*)d_in[13];
    const float* g1  = (const float*)d_in[14];
    const float* be1 = (const float*)d_in[15];
    const float* g2  = (const float*)d_in[16];
    const float* be2 = (const float*)d_in[17];
    float* out = (float*)d_out;

    float *q, *k, *v, *ctx, *x1, *hb;
    cudaGetSymbolAddress((void**)&q, g_q);
    cudaGetSymbolAddress((void**)&k, g_k);
    cudaGetSymbolAddress((void**)&v, g_v);
    cudaGetSymbolAddress((void**)&ctx, g_ctx);
    cudaGetSymbolAddress((void**)&x1, g_x1);
    cudaGetSymbolAddress((void**)&hb, g_hb);

    cudaFuncSetAttribute(tgemm_kernel<0>, cudaFuncAttributeMaxDynamicSharedMemorySize, GEMM_SMEM_BYTES);
    cudaFuncSetAttribute(tgemm_kernel<1>, cudaFuncAttributeMaxDynamicSharedMemorySize, GEMM_SMEM_BYTES);
    cudaFuncSetAttribute(tgemm_kernel<2>, cudaFuncAttributeMaxDynamicSharedMemorySize, GEMM_SMEM_BYTES);
    cudaFuncSetAttribute(flash_tc_kernel, cudaFuncAttributeMaxDynamicSharedMemorySize, FLASH_SMEM_BYTES);

    const dim3 blk(256);
    const dim3 gD(D_ / TBN, NTOK / TBM);     // (8, 64)
    const dim3 gFF(FF_ / TBN, NTOK / TBM);   // (32, 64)

    // QKV projections
    tgemm_kernel<0><<<gD, blk, GEMM_SMEM_BYTES>>>(x, wq, bq, nullptr, q, NTOK, D_, D_);
    tgemm_kernel<0><<<gD, blk, GEMM_SMEM_BYTES>>>(x, wk, bk, nullptr, k, NTOK, D_, D_);
    tgemm_kernel<0><<<gD, blk, GEMM_SMEM_BYTES>>>(x, wv, bv, nullptr, v, NTOK, D_, D_);

    // Flash attention (tensor cores) -> ctx
    flash_tc_kernel<<<dim3(S_ / FBQ, B_ * H_), blk, FLASH_SMEM_BYTES>>>(q, k, v, mask, ctx);

    // atted = ctx @ wm + bm; y1 = x + atted  (into g_k)
    tgemm_kernel<2><<<gD, blk, GEMM_SMEM_BYTES>>>(ctx, wm, bm, x, k, NTOK, D_, D_);
    ln_kernel<<<NTOK, blk>>>(k, g1, be1, x1);

    // FFN
    tgemm_kernel<1><<<gFF, blk, GEMM_SMEM_BYTES>>>(x1, w1, b1, nullptr, hb, NTOK, FF_, D_);
    tgemm_kernel<2><<<gD, blk, GEMM_SMEM_BYTES>>>(hb, w2, b2, x1, v, NTOK, D_, FF_);
    ln_kernel<<<NTOK, blk>>>(v, g2, be2, out);
}

// round 4
// speedup vs baseline: 2.5387x; 1.2489x over previous
#include <cuda_runtime.h>
#include <math.h>
#include <stdint.h>

// Problem constants
#define B_   4
#define S_   2048
#define D_   1024
#define H_   16
#define DH_  64
#define FF_  4096
#define NTOK (B_ * S_)   // 8192

// ---------------------------------------------------------------------------
// Scratch buffers
// ---------------------------------------------------------------------------
__device__ float g_q[(size_t)NTOK * D_];
__device__ float g_k[(size_t)NTOK * D_];
__device__ float g_v[(size_t)NTOK * D_];
__device__ float g_ctx[(size_t)NTOK * D_];
__device__ float g_x1[(size_t)NTOK * D_];
__device__ float g_hb[(size_t)NTOK * FF_];

// ---------------------------------------------------------------------------
// tf32 helpers
// ---------------------------------------------------------------------------
__device__ __forceinline__ float f2tf32(float x) {
    uint32_t y;
    asm("cvt.rna.tf32.f32 %0, %1;" : "=r"(y) : "f"(x));
    return __uint_as_float(y);
}

__device__ __forceinline__ void mma_tf32(float* d, const uint32_t* a, const uint32_t* b) {
    asm volatile(
        "mma.sync.aligned.m16n8k8.row.col.f32.tf32.tf32.f32 "
        "{%0,%1,%2,%3}, {%4,%5,%6,%7}, {%8,%9}, {%0,%1,%2,%3};"
        : "+f"(d[0]), "+f"(d[1]), "+f"(d[2]), "+f"(d[3])
        : "r"(a[0]), "r"(a[1]), "r"(a[2]), "r"(a[3]), "r"(b[0]), "r"(b[1]));
}

// ---------------------------------------------------------------------------
// tf32 tensor-core GEMM body (shared by plain + fused-QKV kernels)
// 128x128x32 CTA tile, 256 threads (8 warps 2x4), warp tile 64x32.
// Double-buffered smem + register prefetch. 2 CTAs/SM.
// ---------------------------------------------------------------------------
#define TBM 128
#define TBN 128
#define TBK 32
#define BPAD 4
#define ASZ 4096
#define BSZ (32 * (128 + BPAD))
#define GEMM_SMEM_BYTES ((ASZ + BSZ) * 2 * 4)

template <int EPI>
__device__ __forceinline__ void tgemm_body(
    const float* __restrict__ A, const float* __restrict__ W,
    const float* __restrict__ bias, const float* __restrict__ res,
    float* __restrict__ C, int M, int N, int K)
{
    extern __shared__ float smem[];
    float* As = smem;
    float* Bs = smem + 2 * ASZ;

    const int tid = threadIdx.x;
    const int lane = tid & 31;
    const int warp = tid >> 5;
    const int wm = warp >> 2;
    const int wn = warp & 3;
    const int bm = blockIdx.y * TBM;
    const int bn = blockIdx.x * TBN;

    const int arow = tid >> 3;
    const int acol = (tid & 7) << 2;
    const int a_ks = acol >> 3;
    const int a_creg = ((acol & 7) >> 2) << 1;
    const int brow = tid >> 5;
    const int bcol = (tid & 31) << 2;

    const float* Ag = A + (size_t)(bm + arow) * K + acol;
    const float* Wg = W + (size_t)brow * N + bn + bcol;

    float acc[4][4][4];
#pragma unroll
    for (int i = 0; i < 4; i++)
#pragma unroll
        for (int j = 0; j < 4; j++)
#pragma unroll
            for (int r = 0; r < 4; r++) acc[i][j][r] = 0.f;

    const int NIT = K / TBK;
    float4 Ar[4], Br[4];

#pragma unroll
    for (int i = 0; i < 4; i++) {
        Ar[i] = *(const float4*)(Ag + (size_t)(i * 32) * K);
        Br[i] = *(const float4*)(Wg + (size_t)(i * 8) * N);
    }

    int buf = 0;
    {
        float* as = As;
        float* bs = Bs;
#pragma unroll
        for (int i = 0; i < 4; i++) {
            const int row = arow + i * 32;
            const int mt = row >> 4;
            const int rb = ((row >> 3) & 1) + a_creg;
            const int base = (((a_ks * 8 + mt) * 32) + ((row & 7) << 2)) * 4 + rb;
            as[base +  0] = f2tf32(Ar[i].x);
            as[base +  4] = f2tf32(Ar[i].y);
            as[base +  8] = f2tf32(Ar[i].z);
            as[base + 12] = f2tf32(Ar[i].w);
            const int k = brow + i * 8;
            float4 bv = make_float4(f2tf32(Br[i].x), f2tf32(Br[i].y),
                                    f2tf32(Br[i].z), f2tf32(Br[i].w));
            *(float4*)(bs + k * (128 + BPAD) + bcol) = bv;
        }
    }
    __syncthreads();

    for (int it = 0; it < NIT; ++it) {
        if (it + 1 < NIT) {
            const int k0 = (it + 1) * TBK;
#pragma unroll
            for (int i = 0; i < 4; i++) {
                Ar[i] = *(const float4*)(Ag + (size_t)k0 + (size_t)(i * 32) * K);
                Br[i] = *(const float4*)(Wg + (size_t)(k0 + i * 8) * N);
            }
        }

        const float* as = As + buf * ASZ;
        const float* bs = Bs + buf * BSZ;
#pragma unroll
        for (int ks = 0; ks < 4; ks++) {
            uint32_t af[4][4];
#pragma unroll
            for (int i = 0; i < 4; i++) {
                const int mt = wm * 4 + i;
                float4 v = *(const float4*)(as + (((ks * 8 + mt) * 32) + lane) * 4);
                af[i][0] = __float_as_uint(v.x);
                af[i][1] = __float_as_uint(v.y);
                af[i][2] = __float_as_uint(v.z);
                af[i][3] = __float_as_uint(v.w);
            }
            uint32_t bf[4][2];
#pragma unroll
            for (int j = 0; j < 4; j++) {
                const int n = wn * 32 + j * 8 + (lane >> 2);
                const int k = ks * 8 + (lane & 3);
                bf[j][0] = __float_as_uint(bs[k * (128 + BPAD) + n]);
                bf[j][1] = __float_as_uint(bs[(k + 4) * (128 + BPAD) + n]);
            }
#pragma unroll
            for (int i = 0; i < 4; i++)
#pragma unroll
                for (int j = 0; j < 4; j++)
                    mma_tf32(acc[i][j], af[i], bf[j]);
        }

        if (it + 1 < NIT) {
            float* asn = As + (buf ^ 1) * ASZ;
            float* bsn = Bs + (buf ^ 1) * BSZ;
#pragma unroll
            for (int i = 0; i < 4; i++) {
                const int row = arow + i * 32;
                const int mt = row >> 4;
                const int rb = ((row >> 3) & 1) + a_creg;
                const int base = (((a_ks * 8 + mt) * 32) + ((row & 7) << 2)) * 4 + rb;
                asn[base +  0] = f2tf32(Ar[i].x);
                asn[base +  4] = f2tf32(Ar[i].y);
                asn[base +  8] = f2tf32(Ar[i].z);
                asn[base + 12] = f2tf32(Ar[i].w);
                const int k = brow + i * 8;
                float4 bv = make_float4(f2tf32(Br[i].x), f2tf32(Br[i].y),
                                        f2tf32(Br[i].z), f2tf32(Br[i].w));
                *(float4*)(bsn + k * (128 + BPAD) + bcol) = bv;
            }
            __syncthreads();
            buf ^= 1;
        }
    }

#pragma unroll
    for (int i = 0; i < 4; i++) {
        const int r0 = bm + wm * 64 + i * 16 + (lane >> 2);
#pragma unroll
        for (int j = 0; j < 4; j++) {
            const int col = bn + wn * 32 + j * 8 + (lane & 3) * 2;
            float2 bi = *(const float2*)(bias + col);
            float o00 = acc[i][j][0] + bi.x;
            float o01 = acc[i][j][1] + bi.y;
            float o10 = acc[i][j][2] + bi.x;
            float o11 = acc[i][j][3] + bi.y;
            if (EPI == 1) {
                o00 = fmaxf(o00, 0.f); o01 = fmaxf(o01, 0.f);
                o10 = fmaxf(o10, 0.f); o11 = fmaxf(o11, 0.f);
            }
            if (EPI == 2) {
                float2 r0v = *(const float2*)(res + (size_t)r0 * N + col);
                float2 r1v = *(const float2*)(res + (size_t)(r0 + 8) * N + col);
                o00 += r0v.x; o01 += r0v.y;
                o10 += r1v.x; o11 += r1v.y;
            }
            *(float2*)(C + (size_t)r0 * N + col) = make_float2(o00, o01);
            *(float2*)(C + (size_t)(r0 + 8) * N + col) = make_float2(o10, o11);
        }
    }
}

template <int EPI>
__global__ __launch_bounds__(256, 2) void tgemm_kernel(
    const float* __restrict__ A, const float* __restrict__ W,
    const float* __restrict__ bias, const float* __restrict__ res,
    float* __restrict__ C, int M, int N, int K)
{
    tgemm_body<EPI>(A, W, bias, res, C, M, N, K);
}

// Fused QKV: grid.z selects which projection this CTA computes.
__global__ __launch_bounds__(256, 2) void tgemm_qkv_kernel(
    const float* __restrict__ x,
    const float* __restrict__ wq, const float* __restrict__ bq, float* __restrict__ q,
    const float* __restrict__ wk, const float* __restrict__ bk, float* __restrict__ k,
    const float* __restrict__ wv, const float* __restrict__ bv, float* __restrict__ v)
{
    if (blockIdx.z == 0)      tgemm_body<0>(x, wq, bq, nullptr, q, NTOK, D_, D_);
    else if (blockIdx.z == 1) tgemm_body<0>(x, wk, bk, nullptr, k, NTOK, D_, D_);
    else                      tgemm_body<0>(x, wv, bv, nullptr, v, NTOK, D_, D_);
}

// ---------------------------------------------------------------------------
// Tensor-core flash attention with software-pipelined K/V tile loads.
// CTA: 128 queries x (b,h). 8 warps x 16 query rows. Key tiles of 64.
// Next tile's K/V staged in registers during current tile's compute.
// ---------------------------------------------------------------------------
#define FBQ 128
#define FBK 64
#define KS_STRIDE 68
#define VS_STRIDE 72
#define PS_STRIDE 68
#define FLASH_SMEM_BYTES ((64 * KS_STRIDE + 64 * VS_STRIDE + 128 * PS_STRIDE) * 4)

__global__ __launch_bounds__(256, 1) void flash_tc_kernel(
    const float* __restrict__ q, const float* __restrict__ k,
    const float* __restrict__ v, const unsigned char* __restrict__ mask,
    float* __restrict__ ctx)
{
    extern __shared__ float fsm[];
    float* Ks = fsm;
    float* Vs = fsm + 64 * KS_STRIDE;
    float* Ps = fsm + 64 * KS_STRIDE + 64 * VS_STRIDE;

    const int tid = threadIdx.x;
    const int lane = tid & 31;
    const int warp = tid >> 5;
    const int bh = blockIdx.y;
    const int b = bh >> 4;
    const int h = bh & 15;
    const int q0 = blockIdx.x * FBQ;
    const size_t base = (size_t)b * S_ * D_ + (size_t)h * DH_;
    const unsigned char* mrow = mask + (size_t)b * S_;

    const int r0 = lane >> 2;
    const int c0 = lane & 3;

    // Per-thread staging coordinates (4 chunks of 256 threads cover 64x64)
    int srow[4], scol[4];
#pragma unroll
    for (int i = 0; i < 4; i++) {
        const int s4 = tid + i * 256;
        srow[i] = s4 >> 4;
        scol[i] = (s4 & 15) << 2;
    }

    // Stage Q tile into Ps (tf32)
    for (int s4 = tid; s4 < FBQ * 16; s4 += 256) {
        const int row = s4 >> 4;
        const int cc = (s4 & 15) << 2;
        float4 qv = *(const float4*)(q + base + (size_t)(q0 + row) * D_ + cc);
        *(float4*)(Ps + row * PS_STRIDE + cc) =
            make_float4(f2tf32(qv.x), f2tf32(qv.y), f2tf32(qv.z), f2tf32(qv.w));
    }
    __syncthreads();

    // Q A-fragments
    uint32_t qf[8][4];
    {
        const float* pw = Ps + (warp * 16) * PS_STRIDE;
#pragma unroll
        for (int ks = 0; ks < 8; ks++) {
            qf[ks][0] = __float_as_uint(pw[r0 * PS_STRIDE + ks * 8 + c0]);
            qf[ks][1] = __float_as_uint(pw[(r0 + 8) * PS_STRIDE + ks * 8 + c0]);
            qf[ks][2] = __float_as_uint(pw[r0 * PS_STRIDE + ks * 8 + c0 + 4]);
            qf[ks][3] = __float_as_uint(pw[(r0 + 8) * PS_STRIDE + ks * 8 + c0 + 4]);
        }
    }
    __syncthreads();  // Ps (Q staging) fully consumed before P overwrites

    float oa[8][4];
    float mx0 = -1e30f, mx1 = -1e30f, l0 = 0.f, l1 = 0.f;
#pragma unroll
    for (int j = 0; j < 8; j++)
#pragma unroll
        for (int r = 0; r < 4; r++) oa[j][r] = 0.f;

    float* Pw = Ps + (warp * 16) * PS_STRIDE;

    // Prologue: stage tile 0 in registers, store to smem
    float4 Kr[4], Vr[4];
#pragma unroll
    for (int i = 0; i < 4; i++) {
        Kr[i] = *(const float4*)(k + base + (size_t)srow[i] * D_ + scol[i]);
        Vr[i] = *(const float4*)(v + base + (size_t)srow[i] * D_ + scol[i]);
    }
#pragma unroll
    for (int i = 0; i < 4; i++) {
        *(float4*)(Ks + srow[i] * KS_STRIDE + scol[i]) =
            make_float4(f2tf32(Kr[i].x), f2tf32(Kr[i].y), f2tf32(Kr[i].z), f2tf32(Kr[i].w));
        *(float4*)(Vs + srow[i] * VS_STRIDE + scol[i]) =
            make_float4(f2tf32(Vr[i].x), f2tf32(Vr[i].y), f2tf32(Vr[i].z), f2tf32(Vr[i].w));
    }
    __syncthreads();

    for (int kt = 0; kt < S_; kt += FBK) {
        const bool has_next = (kt + FBK) < S_;
        // Prefetch next tile into registers (overlaps with compute below)
        if (has_next) {
            const size_t nb = base + (size_t)(kt + FBK) * D_;
#pragma unroll
            for (int i = 0; i < 4; i++) {
                Kr[i] = *(const float4*)(k + nb + (size_t)srow[i] * D_ + scol[i]);
                Vr[i] = *(const float4*)(v + nb + (size_t)srow[i] * D_ + scol[i]);
            }
        }

        // ---- S = Q @ K^T ----
        float sa[8][4];
#pragma unroll
        for (int j = 0; j < 8; j++)
#pragma unroll
            for (int r = 0; r < 4; r++) sa[j][r] = 0.f;

#pragma unroll
        for (int ks = 0; ks < 8; ks++) {
            uint32_t bf[8][2];
#pragma unroll
            for (int j = 0; j < 8; j++) {
                bf[j][0] = __float_as_uint(Ks[(j * 8 + r0) * KS_STRIDE + ks * 8 + c0]);
                bf[j][1] = __float_as_uint(Ks[(j * 8 + r0) * KS_STRIDE + ks * 8 + c0 + 4]);
            }
#pragma unroll
            for (int j = 0; j < 8; j++) mma_tf32(sa[j], qf[ks], bf[j]);
        }

        // ---- scale + mask + row max ----
        float rm0 = -1e30f, rm1 = -1e30f;
#pragma unroll
        for (int j = 0; j < 8; j++) {
            const int col = kt + j * 8 + 2 * c0;
            const bool m0 = mrow[col] != 0;
            const bool m1 = mrow[col + 1] != 0;
            sa[j][0] = m0 ? -1e9f : sa[j][0] * 0.125f;
            sa[j][1] = m1 ? -1e9f : sa[j][1] * 0.125f;
            sa[j][2] = m0 ? -1e9f : sa[j][2] * 0.125f;
            sa[j][3] = m1 ? -1e9f : sa[j][3] * 0.125f;
            rm0 = fmaxf(rm0, fmaxf(sa[j][0], sa[j][1]));
            rm1 = fmaxf(rm1, fmaxf(sa[j][2], sa[j][3]));
        }
        rm0 = fmaxf(rm0, __shfl_xor_sync(0xffffffffu, rm0, 1));
        rm0 = fmaxf(rm0, __shfl_xor_sync(0xffffffffu, rm0, 2));
        rm1 = fmaxf(rm1, __shfl_xor_sync(0xffffffffu, rm1, 1));
        rm1 = fmaxf(rm1, __shfl_xor_sync(0xffffffffu, rm1, 2));

        const float mn0 = fmaxf(mx0, rm0);
        const float mn1 = fmaxf(mx1, rm1);
        const float corr0 = __expf(mx0 - mn0);
        const float corr1 = __expf(mx1 - mn1);
        mx0 = mn0; mx1 = mn1;

        // ---- p = exp(s - m) -> P smem (warp-private), rescale O ----
        float rs0 = 0.f, rs1 = 0.f;
#pragma unroll
        for (int j = 0; j < 8; j++) {
            const float p0 = __expf(sa[j][0] - mn0);
            const float p1 = __expf(sa[j][1] - mn0);
            const float p2 = __expf(sa[j][2] - mn1);
            const float p3 = __expf(sa[j][3] - mn1);
            rs0 += p0 + p1;
            rs1 += p2 + p3;
            *(float2*)(Pw + r0 * PS_STRIDE + j * 8 + 2 * c0) =
                make_float2(f2tf32(p0), f2tf32(p1));
            *(float2*)(Pw + (r0 + 8) * PS_STRIDE + j * 8 + 2 * c0) =
                make_float2(f2tf32(p2), f2tf32(p3));
            oa[j][0] *= corr0; oa[j][1] *= corr0;
            oa[j][2] *= corr1; oa[j][3] *= corr1;
        }
        rs0 += __shfl_xor_sync(0xffffffffu, rs0, 1);
        rs0 += __shfl_xor_sync(0xffffffffu, rs0, 2);
        rs1 += __shfl_xor_sync(0xffffffffu, rs1, 1);
        rs1 += __shfl_xor_sync(0xffffffffu, rs1, 2);
        l0 = l0 * corr0 + rs0;
        l1 = l1 * corr1 + rs1;

        __syncwarp();

        // ---- O += P @ V ----
#pragma unroll
        for (int ks = 0; ks < 8; ks++) {
            uint32_t pf[4];
            pf[0] = __float_as_uint(Pw[r0 * PS_STRIDE + ks * 8 + c0]);
            pf[1] = __float_as_uint(Pw[(r0 + 8) * PS_STRIDE + ks * 8 + c0]);
            pf[2] = __float_as_uint(Pw[r0 * PS_STRIDE + ks * 8 + c0 + 4]);
            pf[3] = __float_as_uint(Pw[(r0 + 8) * PS_STRIDE + ks * 8 + c0 + 4]);
#pragma unroll
            for (int j = 0; j < 8; j++) {
                uint32_t bf2[2];
                bf2[0] = __float_as_uint(Vs[(ks * 8 + c0) * VS_STRIDE + j * 8 + r0]);
                bf2[1] = __float_as_uint(Vs[(ks * 8 + c0 + 4) * VS_STRIDE + j * 8 + r0]);
                mma_tf32(oa[j], pf, bf2);
            }
        }

        // ---- commit prefetched tile to smem ----
        __syncthreads();  // all warps done reading Ks/Vs
        if (has_next) {
#pragma unroll
            for (int i = 0; i < 4; i++) {
                *(float4*)(Ks + srow[i] * KS_STRIDE + scol[i]) =
                    make_float4(f2tf32(Kr[i].x), f2tf32(Kr[i].y), f2tf32(Kr[i].z), f2tf32(Kr[i].w));
                *(float4*)(Vs + srow[i] * VS_STRIDE + scol[i]) =
                    make_float4(f2tf32(Vr[i].x), f2tf32(Vr[i].y), f2tf32(Vr[i].z), f2tf32(Vr[i].w));
            }
            __syncthreads();
        }
    }

    // ---- finalize ----
    const float inv0 = 1.f / l0;
    const float inv1 = 1.f / l1;
    const int row0 = q0 + warp * 16 + r0;
#pragma unroll
    for (int j = 0; j < 8; j++) {
        const int col = j * 8 + 2 * c0;
        *(float2*)(ctx + base + (size_t)row0 * D_ + col) =
            make_float2(oa[j][0] * inv0, oa[j][1] * inv0);
        *(float2*)(ctx + base + (size_t)(row0 + 8) * D_ + col) =
            make_float2(oa[j][2] * inv1, oa[j][3] * inv1);
    }
}

// ---------------------------------------------------------------------------
// LayerNorm (unchanged)
// ---------------------------------------------------------------------------
__global__ __launch_bounds__(256) void ln_kernel(
    const float* __restrict__ in, const float* __restrict__ g,
    const float* __restrict__ be, float* __restrict__ out)
{
    __shared__ float sred[8], ssred[8];
    __shared__ float muSh, rsSh;

    const int row = blockIdx.x;
    const int tid = threadIdx.x;
    const int lane = tid & 31;
    const int wid = tid >> 5;

    const float* p = in + (size_t)row * D_;
    float4 x = *(const float4*)(p + tid * 4);
    float s = x.x + x.y + x.z + x.w;
    float ss = x.x * x.x + x.y * x.y + x.z * x.z + x.w * x.w;

#pragma unroll
    for (int off = 16; off > 0; off >>= 1) {
        s += __shfl_xor_sync(0xffffffffu, s, off);
        ss += __shfl_xor_sync(0xffffffffu, ss, off);
    }
    if (lane == 0) { sred[wid] = s; ssred[wid] = ss; }
    __syncthreads();
    if (wid == 0) {
        float s2 = (lane < 8) ? sred[lane] : 0.f;
        float ss2 = (lane < 8) ? ssred[lane] : 0.f;
#pragma unroll
        for (int off = 4; off > 0; off >>= 1) {
            s2 += __shfl_xor_sync(0xffffffffu, s2, off);
            ss2 += __shfl_xor_sync(0xffffffffu, ss2, off);
        }
        if (lane == 0) {
            const float mu = s2 * (1.f / D_);
            const float var = ss2 * (1.f / D_) - mu * mu;
            muSh = mu;
            rsSh = rsqrtf(var + 1e-6f);
        }
    }
    __syncthreads();

    const float mu = muSh, rs = rsSh;
    float4 gg = *(const float4*)(g + tid * 4);
    float4 bb = *(const float4*)(be + tid * 4);
    float4 y;
    y.x = (x.x - mu) * rs * gg.x + bb.x;
    y.y = (x.y - mu) * rs * gg.y + bb.y;
    y.z = (x.z - mu) * rs * gg.z + bb.z;
    y.w = (x.w - mu) * rs * gg.w + bb.w;
    *(float4*)(out + (size_t)row * D_ + tid * 4) = y;
}

// ---------------------------------------------------------------------------
// Launch
// ---------------------------------------------------------------------------
extern "C" void kernel_launch(void* const* d_in, const int* in_sizes, int n_in,
                              void* d_out, int out_size)
{
    const float* x   = (const float*)d_in[0];
    const unsigned char* mask = (const unsigned char*)d_in[1];
    const float* wq = (const float*)d_in[2];
    const float* bq = (const float*)d_in[3];
    const float* wk = (const float*)d_in[4];
    const float* bk = (const float*)d_in[5];
    const float* wv = (const float*)d_in[6];
    const float* bv = (const float*)d_in[7];
    const float* wm = (const float*)d_in[8];
    const float* bm = (const float*)d_in[9];
    const float* w1 = (const float*)d_in[10];
    const float* b1 = (const float*)d_in[11];
    const float* w2 = (const float*)d_in[12];
    const float* b2 = (const float*)d_in[13];
    const float* g1  = (const float*)d_in[14];
    const float* be1 = (const float*)d_in[15];
    const float* g2  = (const float*)d_in[16];
    const float* be2 = (const float*)d_in[17];
    float* out = (float*)d_out;

    float *q, *k, *v, *ctx, *x1, *hb;
    cudaGetSymbolAddress((void**)&q, g_q);
    cudaGetSymbolAddress((void**)&k, g_k);
    cudaGetSymbolAddress((void**)&v, g_v);
    cudaGetSymbolAddress((void**)&ctx, g_ctx);
    cudaGetSymbolAddress((void**)&x1, g_x1);
    cudaGetSymbolAddress((void**)&hb, g_hb);

    cudaFuncSetAttribute(tgemm_kernel<0>, cudaFuncAttributeMaxDynamicSharedMemorySize, GEMM_SMEM_BYTES);
    cudaFuncSetAttribute(tgemm_kernel<1>, cudaFuncAttributeMaxDynamicSharedMemorySize, GEMM_SMEM_BYTES);
    cudaFuncSetAttribute(tgemm_kernel<2>, cudaFuncAttributeMaxDynamicSharedMemorySize, GEMM_SMEM_BYTES);
    cudaFuncSetAttribute(tgemm_qkv_kernel, cudaFuncAttributeMaxDynamicSharedMemorySize, GEMM_SMEM_BYTES);
    cudaFuncSetAttribute(flash_tc_kernel, cudaFuncAttributeMaxDynamicSharedMemorySize, FLASH_SMEM_BYTES);

    const dim3 blk(256);
    const dim3 gD(D_ / TBN, NTOK / TBM);        // (8, 64)
    const dim3 gQKV(D_ / TBN, NTOK / TBM, 3);   // fused QKV
    const dim3 gFF(FF_ / TBN, NTOK / TBM);      // (32, 64)

    // Fused QKV projections (one launch)
    tgemm_qkv_kernel<<<gQKV, blk, GEMM_SMEM_BYTES>>>(x, wq, bq, q, wk, bk, k, wv, bv, v);

    // Flash attention -> ctx
    flash_tc_kernel<<<dim3(S_ / FBQ, B_ * H_), blk, FLASH_SMEM_BYTES>>>(q, k, v, mask, ctx);

    // atted = ctx @ wm + bm; y1 = x + atted  (into g_k)
    tgemm_kernel<2><<<gD, blk, GEMM_SMEM_BYTES>>>(ctx, wm, bm, x, k, NTOK, D_, D_);
    ln_kernel<<<NTOK, blk>>>(k, g1, be1, x1);

    // FFN
    tgemm_kernel<1><<<gFF, blk, GEMM_SMEM_BYTES>>>(x1, w1, b1, nullptr, hb, NTOK, FF_, D_);
    tgemm_kernel<2><<<gD, blk, GEMM_SMEM_BYTES>>>(hb, w2, b2, x1, v, NTOK, D_, FF_);
    ln_kernel<<<NTOK, blk>>>(v, g2, be2, out);
}

// round 6
// speedup vs baseline: 2.7108x; 1.0678x over previous
#include <cuda_runtime.h>
#include <math.h>
#include <stdint.h>

// Problem constants
#define B_   4
#define S_   2048
#define D_   1024
#define H_   16
#define DH_  64
#define FF_  4096
#define NTOK (B_ * S_)   // 8192

// ---------------------------------------------------------------------------
// Scratch buffers
// ---------------------------------------------------------------------------
__device__ float g_q[(size_t)NTOK * D_];
__device__ float g_k[(size_t)NTOK * D_];
__device__ float g_v[(size_t)NTOK * D_];
__device__ float g_ctx[(size_t)NTOK * D_];
__device__ float g_x1[(size_t)NTOK * D_];
__device__ float g_hb[(size_t)NTOK * FF_];

// ---------------------------------------------------------------------------
// tf32 helpers
// ---------------------------------------------------------------------------
__device__ __forceinline__ float f2tf32(float x) {
    uint32_t y;
    asm("cvt.rna.tf32.f32 %0, %1;" : "=r"(y) : "f"(x));
    return __uint_as_float(y);
}

__device__ __forceinline__ void mma_tf32(float* d, const uint32_t* a, const uint32_t* b) {
    asm volatile(
        "mma.sync.aligned.m16n8k8.row.col.f32.tf32.tf32.f32 "
        "{%0,%1,%2,%3}, {%4,%5,%6,%7}, {%8,%9}, {%0,%1,%2,%3};"
        : "+f"(d[0]), "+f"(d[1]), "+f"(d[2]), "+f"(d[3])
        : "r"(a[0]), "r"(a[1]), "r"(a[2]), "r"(a[3]), "r"(b[0]), "r"(b[1]));
}

__device__ __forceinline__ uint32_t smem_u32(const void* p) {
    uint32_t a;
    asm("{ .reg .u64 t; cvta.to.shared.u64 t, %1; cvt.u32.u64 %0, t; }" : "=r"(a) : "l"(p));
    return a;
}

__device__ __forceinline__ void cpasync16(uint32_t dst, const void* src) {
    asm volatile("cp.async.cg.shared.global [%0], [%1], 16;" :: "r"(dst), "l"(src) : "memory");
}
__device__ __forceinline__ void cpasync_commit() {
    asm volatile("cp.async.commit_group;" ::: "memory");
}
template <int N>
__device__ __forceinline__ void cpasync_wait() {
    asm volatile("cp.async.wait_group %0;" :: "n"(N) : "memory");
}

// ---------------------------------------------------------------------------
// tf32 tensor-core GEMM (round-4 design).
// EPI: 0 = bias + tf32-round output (QKV), 1 = bias+relu, 2 = bias+residual
// ---------------------------------------------------------------------------
#define TBM 128
#define TBN 128
#define TBK 32
#define BPAD 4
#define ASZ 4096
#define BSZ (32 * (128 + BPAD))
#define GEMM_SMEM_BYTES ((ASZ + BSZ) * 2 * 4)

template <int EPI>
__device__ __forceinline__ void tgemm_body(
    const float* __restrict__ A, const float* __restrict__ W,
    const float* __restrict__ bias, const float* __restrict__ res,
    float* __restrict__ C, int M, int N, int K)
{
    extern __shared__ float smem[];
    float* As = smem;
    float* Bs = smem + 2 * ASZ;

    const int tid = threadIdx.x;
    const int lane = tid & 31;
    const int warp = tid >> 5;
    const int wm = warp >> 2;
    const int wn = warp & 3;
    const int bm = blockIdx.y * TBM;
    const int bn = blockIdx.x * TBN;

    const int arow = tid >> 3;
    const int acol = (tid & 7) << 2;
    const int a_ks = acol >> 3;
    const int a_creg = ((acol & 7) >> 2) << 1;
    const int brow = tid >> 5;
    const int bcol = (tid & 31) << 2;

    const float* Ag = A + (size_t)(bm + arow) * K + acol;
    const float* Wg = W + (size_t)brow * N + bn + bcol;

    float acc[4][4][4];
#pragma unroll
    for (int i = 0; i < 4; i++)
#pragma unroll
        for (int j = 0; j < 4; j++)
#pragma unroll
            for (int r = 0; r < 4; r++) acc[i][j][r] = 0.f;

    const int NIT = K / TBK;
    float4 Ar[4], Br[4];

#pragma unroll
    for (int i = 0; i < 4; i++) {
        Ar[i] = *(const float4*)(Ag + (size_t)(i * 32) * K);
        Br[i] = *(const float4*)(Wg + (size_t)(i * 8) * N);
    }

    int buf = 0;
    {
        float* as = As;
        float* bs = Bs;
#pragma unroll
        for (int i = 0; i < 4; i++) {
            const int row = arow + i * 32;
            const int mt = row >> 4;
            const int rb = ((row >> 3) & 1) + a_creg;
            const int base = (((a_ks * 8 + mt) * 32) + ((row & 7) << 2)) * 4 + rb;
            as[base +  0] = f2tf32(Ar[i].x);
            as[base +  4] = f2tf32(Ar[i].y);
            as[base +  8] = f2tf32(Ar[i].z);
            as[base + 12] = f2tf32(Ar[i].w);
            const int k = brow + i * 8;
            float4 bv = make_float4(f2tf32(Br[i].x), f2tf32(Br[i].y),
                                    f2tf32(Br[i].z), f2tf32(Br[i].w));
            *(float4*)(bs + k * (128 + BPAD) + bcol) = bv;
        }
    }
    __syncthreads();

    for (int it = 0; it < NIT; ++it) {
        if (it + 1 < NIT) {
            const int k0 = (it + 1) * TBK;
#pragma unroll
            for (int i = 0; i < 4; i++) {
                Ar[i] = *(const float4*)(Ag + (size_t)k0 + (size_t)(i * 32) * K);
                Br[i] = *(const float4*)(Wg + (size_t)(k0 + i * 8) * N);
            }
        }

        const float* as = As + buf * ASZ;
        const float* bs = Bs + buf * BSZ;
#pragma unroll
        for (int ks = 0; ks < 4; ks++) {
            uint32_t af[4][4];
#pragma unroll
            for (int i = 0; i < 4; i++) {
                const int mt = wm * 4 + i;
                float4 v = *(const float4*)(as + (((ks * 8 + mt) * 32) + lane) * 4);
                af[i][0] = __float_as_uint(v.x);
                af[i][1] = __float_as_uint(v.y);
                af[i][2] = __float_as_uint(v.z);
                af[i][3] = __float_as_uint(v.w);
            }
            uint32_t bf[4][2];
#pragma unroll
            for (int j = 0; j < 4; j++) {
                const int n = wn * 32 + j * 8 + (lane >> 2);
                const int k = ks * 8 + (lane & 3);
                bf[j][0] = __float_as_uint(bs[k * (128 + BPAD) + n]);
                bf[j][1] = __float_as_uint(bs[(k + 4) * (128 + BPAD) + n]);
            }
#pragma unroll
            for (int i = 0; i < 4; i++)
#pragma unroll
                for (int j = 0; j < 4; j++)
                    mma_tf32(acc[i][j], af[i], bf[j]);
        }

        if (it + 1 < NIT) {
            float* asn = As + (buf ^ 1) * ASZ;
            float* bsn = Bs + (buf ^ 1) * BSZ;
#pragma unroll
            for (int i = 0; i < 4; i++) {
                const int row = arow + i * 32;
                const int mt = row >> 4;
                const int rb = ((row >> 3) & 1) + a_creg;
                const int base = (((a_ks * 8 + mt) * 32) + ((row & 7) << 2)) * 4 + rb;
                asn[base +  0] = f2tf32(Ar[i].x);
                asn[base +  4] = f2tf32(Ar[i].y);
                asn[base +  8] = f2tf32(Ar[i].z);
                asn[base + 12] = f2tf32(Ar[i].w);
                const int k = brow + i * 8;
                float4 bv = make_float4(f2tf32(Br[i].x), f2tf32(Br[i].y),
                                        f2tf32(Br[i].z), f2tf32(Br[i].w));
                *(float4*)(bsn + k * (128 + BPAD) + bcol) = bv;
            }
            __syncthreads();
            buf ^= 1;
        }
    }

#pragma unroll
    for (int i = 0; i < 4; i++) {
        const int r0 = bm + wm * 64 + i * 16 + (lane >> 2);
#pragma unroll
        for (int j = 0; j < 4; j++) {
            const int col = bn + wn * 32 + j * 8 + (lane & 3) * 2;
            float2 bi = *(const float2*)(bias + col);
            float o00 = acc[i][j][0] + bi.x;
            float o01 = acc[i][j][1] + bi.y;
            float o10 = acc[i][j][2] + bi.x;
            float o11 = acc[i][j][3] + bi.y;
            if (EPI == 0) {
                // QKV outputs: pre-round to tf32 (rna) so flash can consume raw
                o00 = f2tf32(o00); o01 = f2tf32(o01);
                o10 = f2tf32(o10); o11 = f2tf32(o11);
            }
            if (EPI == 1) {
                o00 = fmaxf(o00, 0.f); o01 = fmaxf(o01, 0.f);
                o10 = fmaxf(o10, 0.f); o11 = fmaxf(o11, 0.f);
            }
            if (EPI == 2) {
                float2 r0v = *(const float2*)(res + (size_t)r0 * N + col);
                float2 r1v = *(const float2*)(res + (size_t)(r0 + 8) * N + col);
                o00 += r0v.x; o01 += r0v.y;
                o10 += r1v.x; o11 += r1v.y;
            }
            *(float2*)(C + (size_t)r0 * N + col) = make_float2(o00, o01);
            *(float2*)(C + (size_t)(r0 + 8) * N + col) = make_float2(o10, o11);
        }
    }
}

template <int EPI>
__global__ __launch_bounds__(256, 2) void tgemm_kernel(
    const float* __restrict__ A, const float* __restrict__ W,
    const float* __restrict__ bias, const float* __restrict__ res,
    float* __restrict__ C, int M, int N, int K)
{
    tgemm_body<EPI>(A, W, bias, res, C, M, N, K);
}

__global__ __launch_bounds__(256, 2) void tgemm_qkv_kernel(
    const float* __restrict__ x,
    const float* __restrict__ wq, const float* __restrict__ bq, float* __restrict__ q,
    const float* __restrict__ wk, const float* __restrict__ bk, float* __restrict__ k,
    const float* __restrict__ wv, const float* __restrict__ bv, float* __restrict__ v)
{
    if (blockIdx.z == 0)      tgemm_body<0>(x, wq, bq, nullptr, q, NTOK, D_, D_);
    else if (blockIdx.z == 1) tgemm_body<0>(x, wk, bk, nullptr, k, NTOK, D_, D_);
    else                      tgemm_body<0>(x, wv, bv, nullptr, v, NTOK, D_, D_);
}

// ---------------------------------------------------------------------------
// Tensor-core flash attention, cp.async double-buffered K/V, 2 CTAs/SM.
// q/k/v are pre-rounded to tf32 by the QKV GEMM epilogue — consumed raw.
// Smem: Ks[2][64][68] + Vs[2][64][72] + Ps[128][68] = 106,496 B.
// ---------------------------------------------------------------------------
#define FBQ 128
#define FBK 64
#define KS_STRIDE 68
#define VS_STRIDE 72
#define PS_STRIDE 68
#define KBUF (64 * KS_STRIDE)
#define VBUF (64 * VS_STRIDE)
#define FLASH_SMEM_BYTES ((2 * KBUF + 2 * VBUF + 128 * PS_STRIDE) * 4)

__global__ __launch_bounds__(256, 2) void flash_tc_kernel(
    const float* __restrict__ q, const float* __restrict__ k,
    const float* __restrict__ v, const unsigned char* __restrict__ mask,
    float* __restrict__ ctx)
{
    extern __shared__ float fsm[];
    float* Ks = fsm;                       // [2][64][68]
    float* Vs = fsm + 2 * KBUF;            // [2][64][72]
    float* Ps = fsm + 2 * KBUF + 2 * VBUF; // [128][68]
    const uint32_t ks_u = smem_u32(Ks);
    const uint32_t vs_u = smem_u32(Vs);

    const int tid = threadIdx.x;
    const int lane = tid & 31;
    const int warp = tid >> 5;
    const int bh = blockIdx.y;
    const int b = bh >> 4;
    const int h = bh & 15;
    const int q0 = blockIdx.x * FBQ;
    const size_t base = (size_t)b * S_ * D_ + (size_t)h * DH_;
    const unsigned char* mrow = mask + (size_t)b * S_;

    const int r0 = lane >> 2;
    const int c0 = lane & 3;

    // Staging coords: 256 threads x 4 chunks cover 64 rows x 64 cols (float4)
    const int srow0 = tid >> 4;            // 0..15 (+ i*16)
    const int scol = (tid & 15) << 2;      // 0..60

    // Stage Q tile into Ps (raw — already tf32)
    for (int s4 = tid; s4 < FBQ * 16; s4 += 256) {
        const int row = s4 >> 4;
        const int cc = (s4 & 15) << 2;
        *(float4*)(Ps + row * PS_STRIDE + cc) =
            *(const float4*)(q + base + (size_t)(q0 + row) * D_ + cc);
    }
    __syncthreads();

    // Q A-fragments
    uint32_t qf[8][4];
    {
        const float* pw = Ps + (warp * 16) * PS_STRIDE;
#pragma unroll
        for (int ks = 0; ks < 8; ks++) {
            qf[ks][0] = __float_as_uint(pw[r0 * PS_STRIDE + ks * 8 + c0]);
            qf[ks][1] = __float_as_uint(pw[(r0 + 8) * PS_STRIDE + ks * 8 + c0]);
            qf[ks][2] = __float_as_uint(pw[r0 * PS_STRIDE + ks * 8 + c0 + 4]);
            qf[ks][3] = __float_as_uint(pw[(r0 + 8) * PS_STRIDE + ks * 8 + c0 + 4]);
        }
    }
    __syncthreads();  // Q staging consumed before P overwrites

    float oa[8][4];
    float mx0 = -1e30f, mx1 = -1e30f, l0 = 0.f, l1 = 0.f;
#pragma unroll
    for (int j = 0; j < 8; j++)
#pragma unroll
        for (int r = 0; r < 4; r++) oa[j][r] = 0.f;

    float* Pw = Ps + (warp * 16) * PS_STRIDE;

    // Prologue: issue tile 0 via cp.async into buffer 0
    {
        const size_t nb = base;
#pragma unroll
        for (int i = 0; i < 4; i++) {
            const int row = srow0 + i * 16;
            cpasync16(ks_u + (uint32_t)(row * KS_STRIDE + scol) * 4,
                      k + nb + (size_t)row * D_ + scol);
            cpasync16(vs_u + (uint32_t)(row * VS_STRIDE + scol) * 4,
                      v + nb + (size_t)row * D_ + scol);
        }
        cpasync_commit();
    }

    const int NT = S_ / FBK;
    for (int t = 0; t < NT; t++) {
        const int kt = t * FBK;
        const bool has_next = (t + 1) < NT;

        // Issue next tile into the other buffer
        if (has_next) {
            const size_t nb = base + (size_t)(kt + FBK) * D_;
            const uint32_t kb = ks_u + (uint32_t)(((t + 1) & 1) * KBUF) * 4;
            const uint32_t vb = vs_u + (uint32_t)(((t + 1) & 1) * VBUF) * 4;
#pragma unroll
            for (int i = 0; i < 4; i++) {
                const int row = srow0 + i * 16;
                cpasync16(kb + (uint32_t)(row * KS_STRIDE + scol) * 4,
                          k + nb + (size_t)row * D_ + scol);
                cpasync16(vb + (uint32_t)(row * VS_STRIDE + scol) * 4,
                          v + nb + (size_t)row * D_ + scol);
            }
            cpasync_commit();
            cpasync_wait<1>();   // current tile's group done
        } else {
            cpasync_wait<0>();
        }
        __syncthreads();

        const float* Kc = Ks + (t & 1) * KBUF;
        const float* Vc = Vs + (t & 1) * VBUF;

        // ---- S = Q @ K^T ----
        float sa[8][4];
#pragma unroll
        for (int j = 0; j < 8; j++)
#pragma unroll
            for (int r = 0; r < 4; r++) sa[j][r] = 0.f;

#pragma unroll
        for (int ks = 0; ks < 8; ks++) {
            uint32_t bf[8][2];
#pragma unroll
            for (int j = 0; j < 8; j++) {
                bf[j][0] = __float_as_uint(Kc[(j * 8 + r0) * KS_STRIDE + ks * 8 + c0]);
                bf[j][1] = __float_as_uint(Kc[(j * 8 + r0) * KS_STRIDE + ks * 8 + c0 + 4]);
            }
#pragma unroll
            for (int j = 0; j < 8; j++) mma_tf32(sa[j], qf[ks], bf[j]);
        }

        // ---- scale + mask + row max ----
        float rm0 = -1e30f, rm1 = -1e30f;
#pragma unroll
        for (int j = 0; j < 8; j++) {
            const int col = kt + j * 8 + 2 * c0;
            const bool m0 = mrow[col] != 0;
            const bool m1 = mrow[col + 1] != 0;
            sa[j][0] = m0 ? -1e9f : sa[j][0] * 0.125f;
            sa[j][1] = m1 ? -1e9f : sa[j][1] * 0.125f;
            sa[j][2] = m0 ? -1e9f : sa[j][2] * 0.125f;
            sa[j][3] = m1 ? -1e9f : sa[j][3] * 0.125f;
            rm0 = fmaxf(rm0, fmaxf(sa[j][0], sa[j][1]));
            rm1 = fmaxf(rm1, fmaxf(sa[j][2], sa[j][3]));
        }
        rm0 = fmaxf(rm0, __shfl_xor_sync(0xffffffffu, rm0, 1));
        rm0 = fmaxf(rm0, __shfl_xor_sync(0xffffffffu, rm0, 2));
        rm1 = fmaxf(rm1, __shfl_xor_sync(0xffffffffu, rm1, 1));
        rm1 = fmaxf(rm1, __shfl_xor_sync(0xffffffffu, rm1, 2));

        const float mn0 = fmaxf(mx0, rm0);
        const float mn1 = fmaxf(mx1, rm1);
        const float corr0 = __expf(mx0 - mn0);
        const float corr1 = __expf(mx1 - mn1);
        mx0 = mn0; mx1 = mn1;

        // ---- p = exp(s - m) -> P smem (warp-private), rescale O ----
        float rs0 = 0.f, rs1 = 0.f;
#pragma unroll
        for (int j = 0; j < 8; j++) {
            const float p0 = __expf(sa[j][0] - mn0);
            const float p1 = __expf(sa[j][1] - mn0);
            const float p2 = __expf(sa[j][2] - mn1);
            const float p3 = __expf(sa[j][3] - mn1);
            rs0 += p0 + p1;
            rs1 += p2 + p3;
            *(float2*)(Pw + r0 * PS_STRIDE + j * 8 + 2 * c0) =
                make_float2(f2tf32(p0), f2tf32(p1));
            *(float2*)(Pw + (r0 + 8) * PS_STRIDE + j * 8 + 2 * c0) =
                make_float2(f2tf32(p2), f2tf32(p3));
            oa[j][0] *= corr0; oa[j][1] *= corr0;
            oa[j][2] *= corr1; oa[j][3] *= corr1;
        }
        rs0 += __shfl_xor_sync(0xffffffffu, rs0, 1);
        rs0 += __shfl_xor_sync(0xffffffffu, rs0, 2);
        rs1 += __shfl_xor_sync(0xffffffffu, rs1, 1);
        rs1 += __shfl_xor_sync(0xffffffffu, rs1, 2);
        l0 = l0 * corr0 + rs0;
        l1 = l1 * corr1 + rs1;

        __syncwarp();

        // ---- O += P @ V ----
#pragma unroll
        for (int ks = 0; ks < 8; ks++) {
            uint32_t pf[4];
            pf[0] = __float_as_uint(Pw[r0 * PS_STRIDE + ks * 8 + c0]);
            pf[1] = __float_as_uint(Pw[(r0 + 8) * PS_STRIDE + ks * 8 + c0]);
            pf[2] = __float_as_uint(Pw[r0 * PS_STRIDE + ks * 8 + c0 + 4]);
            pf[3] = __float_as_uint(Pw[(r0 + 8) * PS_STRIDE + ks * 8 + c0 + 4]);
#pragma unroll
            for (int j = 0; j < 8; j++) {
                uint32_t bf2[2];
                bf2[0] = __float_as_uint(Vc[(ks * 8 + c0) * VS_STRIDE + j * 8 + r0]);
                bf2[1] = __float_as_uint(Vc[(ks * 8 + c0 + 4) * VS_STRIDE + j * 8 + r0]);
                mma_tf32(oa[j], pf, bf2);
            }
        }

        __syncthreads();  // buffer t&1 fully consumed before iter t+1 refills it
    }

    // ---- finalize ----
    const float inv0 = 1.f / l0;
    const float inv1 = 1.f / l1;
    const int row0 = q0 + warp * 16 + r0;
#pragma unroll
    for (int j = 0; j < 8; j++) {
        const int col = j * 8 + 2 * c0;
        *(float2*)(ctx + base + (size_t)row0 * D_ + col) =
            make_float2(oa[j][0] * inv0, oa[j][1] * inv0);
        *(float2*)(ctx + base + (size_t)(row0 + 8) * D_ + col) =
            make_float2(oa[j][2] * inv1, oa[j][3] * inv1);
    }
}

// ---------------------------------------------------------------------------
// LayerNorm (unchanged)
// ---------------------------------------------------------------------------
__global__ __launch_bounds__(256) void ln_kernel(
    const float* __restrict__ in, const float* __restrict__ g,
    const float* __restrict__ be, float* __restrict__ out)
{
    __shared__ float sred[8], ssred[8];
    __shared__ float muSh, rsSh;

    const int row = blockIdx.x;
    const int tid = threadIdx.x;
    const int lane = tid & 31;
    const int wid = tid >> 5;

    const float* p = in + (size_t)row * D_;
    float4 x = *(const float4*)(p + tid * 4);
    float s = x.x + x.y + x.z + x.w;
    float ss = x.x * x.x + x.y * x.y + x.z * x.z + x.w * x.w;

#pragma unroll
    for (int off = 16; off > 0; off >>= 1) {
        s += __shfl_xor_sync(0xffffffffu, s, off);
        ss += __shfl_xor_sync(0xffffffffu, ss, off);
    }
    if (lane == 0) { sred[wid] = s; ssred[wid] = ss; }
    __syncthreads();
    if (wid == 0) {
        float s2 = (lane < 8) ? sred[lane] : 0.f;
        float ss2 = (lane < 8) ? ssred[lane] : 0.f;
#pragma unroll
        for (int off = 4; off > 0; off >>= 1) {
            s2 += __shfl_xor_sync(0xffffffffu, s2, off);
            ss2 += __shfl_xor_sync(0xffffffffu, ss2, off);
        }
        if (lane == 0) {
            const float mu = s2 * (1.f / D_);
            const float var = ss2 * (1.f / D_) - mu * mu;
            muSh = mu;
            rsSh = rsqrtf(var + 1e-6f);
        }
    }
    __syncthreads();

    const float mu = muSh, rs = rsSh;
    float4 gg = *(const float4*)(g + tid * 4);
    float4 bb = *(const float4*)(be + tid * 4);
    float4 y;
    y.x = (x.x - mu) * rs * gg.x + bb.x;
    y.y = (x.y - mu) * rs * gg.y + bb.y;
    y.z = (x.z - mu) * rs * gg.z + bb.z;
    y.w = (x.w - mu) * rs * gg.w + bb.w;
    *(float4*)(out + (size_t)row * D_ + tid * 4) = y;
}

// ---------------------------------------------------------------------------
// Launch
// ---------------------------------------------------------------------------
extern "C" void kernel_launch(void* const* d_in, const int* in_sizes, int n_in,
                              void* d_out, int out_size)
{
    const float* x   = (const float*)d_in[0];
    const unsigned char* mask = (const unsigned char*)d_in[1];
    const float* wq = (const float*)d_in[2];
    const float* bq = (const float*)d_in[3];
    const float* wk = (const float*)d_in[4];
    const float* bk = (const float*)d_in[5];
    const float* wv = (const float*)d_in[6];
    const float* bv = (const float*)d_in[7];
    const float* wm = (const float*)d_in[8];
    const float* bm = (const float*)d_in[9];
    const float* w1 = (const float*)d_in[10];
    const float* b1 = (const float*)d_in[11];
    const float* w2 = (const float*)d_in[12];
    const float* b2 = (const float*)d_in[13];
    const float* g1  = (const float*)d_in[14];
    const float* be1 = (const float*)d_in[15];
    const float* g2  = (const float*)d_in[16];
    const float* be2 = (const float*)d_in[17];
    float* out = (float*)d_out;

    float *q, *k, *v, *ctx, *x1, *hb;
    cudaGetSymbolAddress((void**)&q, g_q);
    cudaGetSymbolAddress((void**)&k, g_k);
    cudaGetSymbolAddress((void**)&v, g_v);
    cudaGetSymbolAddress((void**)&ctx, g_ctx);
    cudaGetSymbolAddress((void**)&x1, g_x1);
    cudaGetSymbolAddress((void**)&hb, g_hb);

    cudaFuncSetAttribute(tgemm_kernel<0>, cudaFuncAttributeMaxDynamicSharedMemorySize, GEMM_SMEM_BYTES);
    cudaFuncSetAttribute(tgemm_kernel<1>, cudaFuncAttributeMaxDynamicSharedMemorySize, GEMM_SMEM_BYTES);
    cudaFuncSetAttribute(tgemm_kernel<2>, cudaFuncAttributeMaxDynamicSharedMemorySize, GEMM_SMEM_BYTES);
    cudaFuncSetAttribute(tgemm_qkv_kernel, cudaFuncAttributeMaxDynamicSharedMemorySize, GEMM_SMEM_BYTES);
    cudaFuncSetAttribute(flash_tc_kernel, cudaFuncAttributeMaxDynamicSharedMemorySize, FLASH_SMEM_BYTES);

    const dim3 blk(256);
    const dim3 gD(D_ / TBN, NTOK / TBM);        // (8, 64)
    const dim3 gQKV(D_ / TBN, NTOK / TBM, 3);   // fused QKV
    const dim3 gFF(FF_ / TBN, NTOK / TBM);      // (32, 64)

    // Fused QKV projections (outputs tf32-rounded)
    tgemm_qkv_kernel<<<gQKV, blk, GEMM_SMEM_BYTES>>>(x, wq, bq, q, wk, bk, k, wv, bv, v);

    // Flash attention -> ctx
    flash_tc_kernel<<<dim3(S_ / FBQ, B_ * H_), blk, FLASH_SMEM_BYTES>>>(q, k, v, mask, ctx);

    // atted = ctx @ wm + bm; y1 = x + atted  (into g_k)
    tgemm_kernel<2><<<gD, blk, GEMM_SMEM_BYTES>>>(ctx, wm, bm, x, k, NTOK, D_, D_);
    ln_kernel<<<NTOK, blk>>>(k, g1, be1, x1);

    // FFN
    tgemm_kernel<1><<<gFF, blk, GEMM_SMEM_BYTES>>>(x1, w1, b1, nullptr, hb, NTOK, FF_, D_);
    tgemm_kernel<2><<<gD, blk, GEMM_SMEM_BYTES>>>(hb, w2, b2, x1, v, NTOK, D_, FF_);
    ln_kernel<<<NTOK, blk>>>(v, g2, be2, out);
}

// round 8
// speedup vs baseline: 5.0004x; 1.8446x over previous
#include <cuda_runtime.h>
#include <cuda_fp16.h>
#include <math.h>
#include <stdint.h>

// Problem constants
#define B_   4
#define S_   2048
#define D_   1024
#define H_   16
#define DH_  64
#define FF_  4096
#define NTOK (B_ * S_)   // 8192

// ---------------------------------------------------------------------------
// Scratch buffers
// ---------------------------------------------------------------------------
__device__ float  g_v[(size_t)NTOK * D_];     // v fp32 from QKV gemm; reused as y1 after flash
__device__ float  g_ctx[(size_t)NTOK * D_];   // flash out; reused as ffn2 out
__device__ float  g_x1[(size_t)NTOK * D_];
__device__ float  g_hb[(size_t)NTOK * FF_];
__device__ __half g_qh[(size_t)NTOK * D_];
__device__ __half g_kh[(size_t)NTOK * D_];
__device__ __half g_vt[(size_t)NTOK * D_];    // [b*H+h][64 dh][2048 s]

// ---------------------------------------------------------------------------
// helpers
// ---------------------------------------------------------------------------
__device__ __forceinline__ void mma_f16(float* d, const uint32_t* a, const uint32_t* b) {
    asm volatile(
        "mma.sync.aligned.m16n8k16.row.col.f32.f16.f16.f32 "
        "{%0,%1,%2,%3}, {%4,%5,%6,%7}, {%8,%9}, {%0,%1,%2,%3};"
        : "+f"(d[0]), "+f"(d[1]), "+f"(d[2]), "+f"(d[3])
        : "r"(a[0]), "r"(a[1]), "r"(a[2]), "r"(a[3]), "r"(b[0]), "r"(b[1]));
}

__device__ __forceinline__ uint32_t smem_u32(const void* p) {
    uint32_t a;
    asm("{ .reg .u64 t; cvta.to.shared.u64 t, %1; cvt.u32.u64 %0, t; }" : "=r"(a) : "l"(p));
    return a;
}

__device__ __forceinline__ void cpasync16(uint32_t dst, const void* src) {
    asm volatile("cp.async.cg.shared.global [%0], [%1], 16;" :: "r"(dst), "l"(src) : "memory");
}
__device__ __forceinline__ void cpasync_commit() {
    asm volatile("cp.async.commit_group;" ::: "memory");
}
template <int N>
__device__ __forceinline__ void cpasync_wait() {
    asm volatile("cp.async.wait_group %0;" :: "n"(N) : "memory");
}

__device__ __forceinline__ uint32_t h2u(__half2 h) {
    return *reinterpret_cast<uint32_t*>(&h);
}

// ---------------------------------------------------------------------------
// fp16 tensor-core GEMM: C[M,N] = A[M,K] @ W[K,N] (+bias, relu/residual).
// CTA 128x128x32, 256 thr (8 warps 2x4), warp tile 64x32, m16n8k16.
// A smem: frag-permuted [ks(2)][mt(8)][lane(32)][8 halfs]  (4096 halfs/buf)
// B smem: frag-permuted [ks(2)][nt(16)][lane(32)][4 halfs] +4 pad/tile
// EPI: 0 = bias, 1 = bias+relu, 2 = bias+residual.  HOUT: fp16 output.
// ---------------------------------------------------------------------------
#define AHS 4096
#define BHS (32 * 132)
#define GEMM_SMEM_BYTES ((2 * AHS + 2 * BHS) * 2)

template <int EPI, bool HOUT>
__device__ __forceinline__ void tgemm_body(
    const float* __restrict__ A, const float* __restrict__ W,
    const float* __restrict__ bias, const float* __restrict__ res,
    void* __restrict__ Cv, int M, int N, int K)
{
    extern __shared__ __half hsm[];
    __half* As = hsm;              // [2][AHS]
    __half* Bs = hsm + 2 * AHS;    // [2][BHS]

    const int tid = threadIdx.x;
    const int lane = tid & 31;
    const int warp = tid >> 5;
    const int wm = warp >> 2;      // 0..1
    const int wn = warp & 3;       // 0..3
    const int bm = blockIdx.y * 128;
    const int bn = blockIdx.x * 128;

    const int arow = tid >> 3;
    const int acol = (tid & 7) << 2;
    const int brow = tid >> 5;
    const int bcol = (tid & 31) << 2;

    const float* Ag = A + (size_t)(bm + arow) * K + acol;
    const float* Wg = W + (size_t)brow * N + bn + bcol;

    const int a_ks = acol >> 4;
    const int a_j = acol & 15;
    const int a_lb = (a_j & 7) >> 1;
    const int a_rj = 2 * (a_j >> 3);
    const int b_nt = bcol >> 3;
    const int b_j0 = bcol & 7;

    float acc[4][4][4];
#pragma unroll
    for (int i = 0; i < 4; i++)
#pragma unroll
        for (int j = 0; j < 4; j++)
#pragma unroll
            for (int r = 0; r < 4; r++) acc[i][j][r] = 0.f;

    const int NIT = K / 32;
    float4 Ar[4], Br[4];

#pragma unroll
    for (int i = 0; i < 4; i++) {
        Ar[i] = *(const float4*)(Ag + (size_t)(i * 32) * K);
        Br[i] = *(const float4*)(Wg + (size_t)(i * 8) * N);
    }

    int buf = 0;
    {
        __half* as = As;
        __half* bs = Bs;
#pragma unroll
        for (int i = 0; i < 4; i++) {
            const int row = arow + i * 32;
            const int i_loc = row & 15;
            const int mt = row >> 4;
            const int lane0 = (i_loc & 7) * 4 + a_lb;
            const int reg = (i_loc >> 3) + a_rj;
            __half* tb = as + (a_ks * 8 + mt) * 256;
            *(__half2*)(tb + lane0 * 8 + reg * 2) = __floats2half2_rn(Ar[i].x, Ar[i].y);
            *(__half2*)(tb + (lane0 + 1) * 8 + reg * 2) = __floats2half2_rn(Ar[i].z, Ar[i].w);

            const int k = brow + i * 8;
            const int ks = k >> 4;
            const int k_loc = k & 15;
            const int reg_b = k_loc >> 3;
            const int hb2 = k_loc & 1;
            const int kk = (k_loc & 7) >> 1;
            __half* tbb = bs + (ks * 16 + b_nt) * 132;
            const float bvv[4] = {Br[i].x, Br[i].y, Br[i].z, Br[i].w};
#pragma unroll
            for (int t = 0; t < 4; t++) {
                const int lane_b = (b_j0 + t) * 4 + kk;
                tbb[lane_b * 4 + reg_b * 2 + hb2] = __float2half_rn(bvv[t]);
            }
        }
    }
    __syncthreads();

    for (int it = 0; it < NIT; ++it) {
        if (it + 1 < NIT) {
            const int k0 = (it + 1) * 32;
#pragma unroll
            for (int i = 0; i < 4; i++) {
                Ar[i] = *(const float4*)(Ag + (size_t)k0 + (size_t)(i * 32) * K);
                Br[i] = *(const float4*)(Wg + (size_t)(k0 + i * 8) * N);
            }
        }

        const __half* as = As + buf * AHS;
        const __half* bs = Bs + buf * BHS;
#pragma unroll
        for (int ks = 0; ks < 2; ks++) {
            uint4 av[4];
#pragma unroll
            for (int i = 0; i < 4; i++)
                av[i] = *(const uint4*)(as + ((ks * 8 + wm * 4 + i) * 256 + lane * 8));
            uint2 bv[4];
#pragma unroll
            for (int j = 0; j < 4; j++)
                bv[j] = *(const uint2*)(bs + ((ks * 16 + wn * 4 + j) * 132 + lane * 4));
#pragma unroll
            for (int i = 0; i < 4; i++)
#pragma unroll
                for (int j = 0; j < 4; j++)
                    mma_f16(acc[i][j], (const uint32_t*)&av[i], (const uint32_t*)&bv[j]);
        }

        if (it + 1 < NIT) {
            __half* as2 = As + (buf ^ 1) * AHS;
            __half* bs2 = Bs + (buf ^ 1) * BHS;
#pragma unroll
            for (int i = 0; i < 4; i++) {
                const int row = arow + i * 32;
                const int i_loc = row & 15;
                const int mt = row >> 4;
                const int lane0 = (i_loc & 7) * 4 + a_lb;
                const int reg = (i_loc >> 3) + a_rj;
                __half* tb = as2 + (a_ks * 8 + mt) * 256;
                *(__half2*)(tb + lane0 * 8 + reg * 2) = __floats2half2_rn(Ar[i].x, Ar[i].y);
                *(__half2*)(tb + (lane0 + 1) * 8 + reg * 2) = __floats2half2_rn(Ar[i].z, Ar[i].w);

                const int k = brow + i * 8;
                const int ks = k >> 4;
                const int k_loc = k & 15;
                const int reg_b = k_loc >> 3;
                const int hb2 = k_loc & 1;
                const int kk = (k_loc & 7) >> 1;
                __half* tbb = bs2 + (ks * 16 + b_nt) * 132;
                const float bvv[4] = {Br[i].x, Br[i].y, Br[i].z, Br[i].w};
#pragma unroll
                for (int t = 0; t < 4; t++) {
                    const int lane_b = (b_j0 + t) * 4 + kk;
                    tbb[lane_b * 4 + reg_b * 2 + hb2] = __float2half_rn(bvv[t]);
                }
            }
            __syncthreads();
            buf ^= 1;
        }
    }

    // Epilogue
#pragma unroll
    for (int i = 0; i < 4; i++) {
        const int r0 = bm + wm * 64 + i * 16 + (lane >> 2);
#pragma unroll
        for (int j = 0; j < 4; j++) {
            const int col = bn + wn * 32 + j * 8 + (lane & 3) * 2;
            float2 bi = *(const float2*)(bias + col);
            float o00 = acc[i][j][0] + bi.x;
            float o01 = acc[i][j][1] + bi.y;
            float o10 = acc[i][j][2] + bi.x;
            float o11 = acc[i][j][3] + bi.y;
            if (EPI == 1) {
                o00 = fmaxf(o00, 0.f); o01 = fmaxf(o01, 0.f);
                o10 = fmaxf(o10, 0.f); o11 = fmaxf(o11, 0.f);
            }
            if (EPI == 2) {
                float2 r0v = *(const float2*)(res + (size_t)r0 * N + col);
                float2 r1v = *(const float2*)(res + (size_t)(r0 + 8) * N + col);
                o00 += r0v.x; o01 += r0v.y;
                o10 += r1v.x; o11 += r1v.y;
            }
            if (HOUT) {
                __half* Ch = (__half*)Cv;
                *(__half2*)(Ch + (size_t)r0 * N + col) = __floats2half2_rn(o00, o01);
                *(__half2*)(Ch + (size_t)(r0 + 8) * N + col) = __floats2half2_rn(o10, o11);
            } else {
                float* Cf = (float*)Cv;
                *(float2*)(Cf + (size_t)r0 * N + col) = make_float2(o00, o01);
                *(float2*)(Cf + (size_t)(r0 + 8) * N + col) = make_float2(o10, o11);
            }
        }
    }
}

template <int EPI>
__global__ __launch_bounds__(256, 2) void tgemm_kernel(
    const float* __restrict__ A, const float* __restrict__ W,
    const float* __restrict__ bias, const float* __restrict__ res,
    float* __restrict__ C, int M, int N, int K)
{
    tgemm_body<EPI, false>(A, W, bias, res, C, M, N, K);
}

__global__ __launch_bounds__(256, 2) void tgemm_qkv_kernel(
    const float* __restrict__ x,
    const float* __restrict__ wq, const float* __restrict__ bq, __half* __restrict__ qh,
    const float* __restrict__ wk, const float* __restrict__ bk, __half* __restrict__ kh,
    const float* __restrict__ wv, const float* __restrict__ bv, float* __restrict__ v)
{
    if (blockIdx.z == 0)      tgemm_body<0, true>(x, wq, bq, nullptr, qh, NTOK, D_, D_);
    else if (blockIdx.z == 1) tgemm_body<0, true>(x, wk, bk, nullptr, kh, NTOK, D_, D_);
    else                      tgemm_body<0, false>(x, wv, bv, nullptr, v, NTOK, D_, D_);
}

// ---------------------------------------------------------------------------
// V transpose-convert: g_v fp32 [tok][D] -> g_vt fp16 [b*H+h][dh][s]
// ---------------------------------------------------------------------------
__global__ __launch_bounds__(256) void vtrans_kernel(
    const float* __restrict__ v, __half* __restrict__ vt)
{
    __shared__ float t[32][33];
    const int c0 = blockIdx.x * 32;
    const int r0 = blockIdx.y * 32;
    const int x = threadIdx.x, y = threadIdx.y;
#pragma unroll
    for (int i = 0; i < 32; i += 8)
        t[y + i][x] = v[(size_t)(r0 + y + i) * D_ + c0 + x];
    __syncthreads();
    const int b = r0 >> 11;
    const int s = (r0 & 2047) + x;
    const int h = c0 >> 6;
    const int d0 = c0 & 63;
#pragma unroll
    for (int i = 0; i < 32; i += 8) {
        const int d = d0 + y + i;
        vt[((size_t)(b * 16 + h) * 64 + d) * (size_t)S_ + s] = __float2half_rn(t[x][y + i]);
    }
}

// ---------------------------------------------------------------------------
// fp16 flash attention. CTA: 128 q-rows x (b,h); 8 warps x 16 rows.
// K tiles [key][d] fp16, V^T tiles [d][key] fp16 via 3-stage cp.async ring.
// P stays in registers (S-acc layout == PV A-frag layout).
// ---------------------------------------------------------------------------
#define FBK 64
#define KROW 72
#define KBUF (64 * KROW)
#define NSTAGE 3
#define FLASH_SMEM_BYTES (NSTAGE * 2 * KBUF * 2)

__global__ __launch_bounds__(256, 2) void flash_fp16_kernel(
    const __half* __restrict__ qh, const __half* __restrict__ kh,
    const __half* __restrict__ vt, const unsigned char* __restrict__ mask,
    float* __restrict__ ctx)
{
    extern __shared__ __half fh[];
    __half* Kf = fh;                  // [NSTAGE][64][72]
    __half* Vf = fh + NSTAGE * KBUF;  // [NSTAGE][64][72]
    const uint32_t ks_u = smem_u32(Kf);
    const uint32_t vs_u = smem_u32(Vf);

    const int tid = threadIdx.x;
    const int lane = tid & 31;
    const int warp = tid >> 5;
    const int bh = blockIdx.y;
    const int b = bh >> 4;
    const int h = bh & 15;
    const int q0 = blockIdx.x * 128;
    const int hoff = h * DH_;
    const unsigned char* mrow = mask + (size_t)b * S_;

    const int r0 = lane >> 2;   // 0..7
    const int c0 = lane & 3;    // 0..3

    // ---- Q A-frags from global fp16 (one-time) ----
    uint32_t qf[4][4];
    {
        const size_t rowa = (size_t)(b * S_ + q0 + warp * 16 + r0) * D_ + hoff;
#pragma unroll
        for (int ks = 0; ks < 4; ks++) {
            const int c = ks * 16 + 2 * c0;
            qf[ks][0] = *(const uint32_t*)(qh + rowa + c);
            qf[ks][1] = *(const uint32_t*)(qh + rowa + 8 * D_ + c);
            qf[ks][2] = *(const uint32_t*)(qh + rowa + c + 8);
            qf[ks][3] = *(const uint32_t*)(qh + rowa + 8 * D_ + c + 8);
        }
    }

    float oa[8][4];
    float mx0 = -1e30f, mx1 = -1e30f, l0 = 0.f, l1 = 0.f;
#pragma unroll
    for (int j = 0; j < 8; j++)
#pragma unroll
        for (int r = 0; r < 4; r++) oa[j][r] = 0.f;

    const int id0 = tid, id1 = tid + 256;
    const int krow0 = id0 >> 3, kch0 = id0 & 7;
    const int krow1 = id1 >> 3, kch1 = id1 & 7;

    const __half* kbase = kh + (size_t)b * S_ * D_ + hoff;
    const __half* vbase = vt + (size_t)bh * 64 * S_;

    const int NT = S_ / FBK;

    // prologue: issue tiles 0 and 1
#pragma unroll
    for (int t = 0; t < 2; t++) {
        const int kt = t * FBK;
        const uint32_t kdst = ks_u + (uint32_t)(t * KBUF) * 2;
        const uint32_t vdst = vs_u + (uint32_t)(t * KBUF) * 2;
        cpasync16(kdst + (uint32_t)(krow0 * KROW) * 2 + kch0 * 16,
                  kbase + (size_t)(kt + krow0) * D_ + kch0 * 8);
        cpasync16(kdst + (uint32_t)(krow1 * KROW) * 2 + kch1 * 16,
                  kbase + (size_t)(kt + krow1) * D_ + kch1 * 8);
        cpasync16(vdst + (uint32_t)(krow0 * KROW) * 2 + kch0 * 16,
                  vbase + (size_t)krow0 * S_ + kt + kch0 * 8);
        cpasync16(vdst + (uint32_t)(krow1 * KROW) * 2 + kch1 * 16,
                  vbase + (size_t)krow1 * S_ + kt + kch1 * 8);
        cpasync_commit();
    }

    for (int t = 0; t < NT; t++) {
        const int kt = t * FBK;
        if (t + 2 < NT) {
            const int nkt = kt + 2 * FBK;
            const int st = (t + 2) % NSTAGE;
            const uint32_t kdst = ks_u + (uint32_t)(st * KBUF) * 2;
            const uint32_t vdst = vs_u + (uint32_t)(st * KBUF) * 2;
            cpasync16(kdst + (uint32_t)(krow0 * KROW) * 2 + kch0 * 16,
                      kbase + (size_t)(nkt + krow0) * D_ + kch0 * 8);
            cpasync16(kdst + (uint32_t)(krow1 * KROW) * 2 + kch1 * 16,
                      kbase + (size_t)(nkt + krow1) * D_ + kch1 * 8);
            cpasync16(vdst + (uint32_t)(krow0 * KROW) * 2 + kch0 * 16,
                      vbase + (size_t)krow0 * S_ + nkt + kch0 * 8);
            cpasync16(vdst + (uint32_t)(krow1 * KROW) * 2 + kch1 * 16,
                      vbase + (size_t)krow1 * S_ + nkt + kch1 * 8);
            cpasync_commit();
            cpasync_wait<2>();
        } else if (t + 1 < NT) {
            cpasync_wait<1>();
        } else {
            cpasync_wait<0>();
        }
        __syncthreads();

        const __half* Kc = Kf + (t % NSTAGE) * KBUF;
        const __half* Vc = Vf + (t % NSTAGE) * KBUF;

        // ---- S = Q @ K^T ----
        float sa[8][4];
#pragma unroll
        for (int j = 0; j < 8; j++)
#pragma unroll
            for (int r = 0; r < 4; r++) sa[j][r] = 0.f;

#pragma unroll
        for (int ks = 0; ks < 4; ks++) {
            const int kc = ks * 16 + 2 * c0;
#pragma unroll
            for (int j = 0; j < 8; j++) {
                const __half* kp = Kc + (j * 8 + r0) * KROW + kc;
                uint32_t bb[2];
                bb[0] = *(const uint32_t*)kp;
                bb[1] = *(const uint32_t*)(kp + 8);
                mma_f16(sa[j], qf[ks], bb);
            }
        }

        // ---- scale + mask + row max ----
        float rm0 = -1e30f, rm1 = -1e30f;
#pragma unroll
        for (int j = 0; j < 8; j++) {
            const int col = kt + j * 8 + 2 * c0;
            const bool m0 = mrow[col] != 0;
            const bool m1 = mrow[col + 1] != 0;
            sa[j][0] = m0 ? -1e9f : sa[j][0] * 0.125f;
            sa[j][1] = m1 ? -1e9f : sa[j][1] * 0.125f;
            sa[j][2] = m0 ? -1e9f : sa[j][2] * 0.125f;
            sa[j][3] = m1 ? -1e9f : sa[j][3] * 0.125f;
            rm0 = fmaxf(rm0, fmaxf(sa[j][0], sa[j][1]));
            rm1 = fmaxf(rm1, fmaxf(sa[j][2], sa[j][3]));
        }
        rm0 = fmaxf(rm0, __shfl_xor_sync(0xffffffffu, rm0, 1));
        rm0 = fmaxf(rm0, __shfl_xor_sync(0xffffffffu, rm0, 2));
        rm1 = fmaxf(rm1, __shfl_xor_sync(0xffffffffu, rm1, 1));
        rm1 = fmaxf(rm1, __shfl_xor_sync(0xffffffffu, rm1, 2));

        const float mn0 = fmaxf(mx0, rm0);
        const float mn1 = fmaxf(mx1, rm1);
        const float corr0 = __expf(mx0 - mn0);
        const float corr1 = __expf(mx1 - mn1);
        mx0 = mn0; mx1 = mn1;

        // ---- p = exp(s - m) in registers; rescale O; row sums ----
        float rs0 = 0.f, rs1 = 0.f;
#pragma unroll
        for (int j = 0; j < 8; j++) {
            sa[j][0] = __expf(sa[j][0] - mn0);
            sa[j][1] = __expf(sa[j][1] - mn0);
            sa[j][2] = __expf(sa[j][2] - mn1);
            sa[j][3] = __expf(sa[j][3] - mn1);
            rs0 += sa[j][0] + sa[j][1];
            rs1 += sa[j][2] + sa[j][3];
            oa[j][0] *= corr0; oa[j][1] *= corr0;
            oa[j][2] *= corr1; oa[j][3] *= corr1;
        }
        rs0 += __shfl_xor_sync(0xffffffffu, rs0, 1);
        rs0 += __shfl_xor_sync(0xffffffffu, rs0, 2);
        rs1 += __shfl_xor_sync(0xffffffffu, rs1, 1);
        rs1 += __shfl_xor_sync(0xffffffffu, rs1, 2);
        l0 = l0 * corr0 + rs0;
        l1 = l1 * corr1 + rs1;

        // ---- O += P @ V : P converts in-register to A-frags ----
#pragma unroll
        for (int ks = 0; ks < 4; ks++) {
            uint32_t pf[4];
            pf[0] = h2u(__floats2half2_rn(sa[2 * ks][0], sa[2 * ks][1]));
            pf[1] = h2u(__floats2half2_rn(sa[2 * ks][2], sa[2 * ks][3]));
            pf[2] = h2u(__floats2half2_rn(sa[2 * ks + 1][0], sa[2 * ks + 1][1]));
            pf[3] = h2u(__floats2half2_rn(sa[2 * ks + 1][2], sa[2 * ks + 1][3]));
            const int kc = ks * 16 + 2 * c0;
#pragma unroll
            for (int j = 0; j < 8; j++) {
                const __half* vp = Vc + (j * 8 + r0) * KROW + kc;
                uint32_t bb[2];
                bb[0] = *(const uint32_t*)vp;
                bb[1] = *(const uint32_t*)(vp + 8);
                mma_f16(oa[j], pf, bb);
            }
        }

        __syncthreads();  // stage fully consumed before ring reuse
    }

    // ---- finalize ----
    const float inv0 = 1.f / l0;
    const float inv1 = 1.f / l1;
    const int row0 = q0 + warp * 16 + r0;
    const size_t obase = (size_t)b * S_ * D_ + hoff;
#pragma unroll
    for (int j = 0; j < 8; j++) {
        const int col = j * 8 + 2 * c0;
        *(float2*)(ctx + obase + (size_t)row0 * D_ + col) =
            make_float2(oa[j][0] * inv0, oa[j][1] * inv0);
        *(float2*)(ctx + obase + (size_t)(row0 + 8) * D_ + col) =
            make_float2(oa[j][2] * inv1, oa[j][3] * inv1);
    }
}

// ---------------------------------------------------------------------------
// LayerNorm (unchanged)
// ---------------------------------------------------------------------------
__global__ __launch_bounds__(256) void ln_kernel(
    const float* __restrict__ in, const float* __restrict__ g,
    const float* __restrict__ be, float* __restrict__ out)
{
    __shared__ float sred[8], ssred[8];
    __shared__ float muSh, rsSh;

    const int row = blockIdx.x;
    const int tid = threadIdx.x;
    const int lane = tid & 31;
    const int wid = tid >> 5;

    const float* p = in + (size_t)row * D_;
    float4 x = *(const float4*)(p + tid * 4);
    float s = x.x + x.y + x.z + x.w;
    float ss = x.x * x.x + x.y * x.y + x.z * x.z + x.w * x.w;

#pragma unroll
    for (int off = 16; off > 0; off >>= 1) {
        s += __shfl_xor_sync(0xffffffffu, s, off);
        ss += __shfl_xor_sync(0xffffffffu, ss, off);
    }
    if (lane == 0) { sred[wid] = s; ssred[wid] = ss; }
    __syncthreads();
    if (wid == 0) {
        float s2 = (lane < 8) ? sred[lane] : 0.f;
        float ss2 = (lane < 8) ? ssred[lane] : 0.f;
#pragma unroll
        for (int off = 4; off > 0; off >>= 1) {
            s2 += __shfl_xor_sync(0xffffffffu, s2, off);
            ss2 += __shfl_xor_sync(0xffffffffu, ss2, off);
        }
        if (lane == 0) {
            const float mu = s2 * (1.f / D_);
            const float var = ss2 * (1.f / D_) - mu * mu;
            muSh = mu;
            rsSh = rsqrtf(var + 1e-6f);
        }
    }
    __syncthreads();

    const float mu = muSh, rs = rsSh;
    float4 gg = *(const float4*)(g + tid * 4);
    float4 bb = *(const float4*)(be + tid * 4);
    float4 y;
    y.x = (x.x - mu) * rs * gg.x + bb.x;
    y.y = (x.y - mu) * rs * gg.y + bb.y;
    y.z = (x.z - mu) * rs * gg.z + bb.z;
    y.w = (x.w - mu) * rs * gg.w + bb.w;
    *(float4*)(out + (size_t)row * D_ + tid * 4) = y;
}

// ---------------------------------------------------------------------------
// Launch
// ---------------------------------------------------------------------------
extern "C" void kernel_launch(void* const* d_in, const int* in_sizes, int n_in,
                              void* d_out, int out_size)
{
    const float* x   = (const float*)d_in[0];
    const unsigned char* mask = (const unsigned char*)d_in[1];
    const float* wq = (const float*)d_in[2];
    const float* bq = (const float*)d_in[3];
    const float* wk = (const float*)d_in[4];
    const float* bk = (const float*)d_in[5];
    const float* wv = (const float*)d_in[6];
    const float* bv = (const float*)d_in[7];
    const float* wm = (const float*)d_in[8];
    const float* bm = (const float*)d_in[9];
    const float* w1 = (const float*)d_in[10];
    const float* b1 = (const float*)d_in[11];
    const float* w2 = (const float*)d_in[12];
    const float* b2 = (const float*)d_in[13];
    const float* g1  = (const float*)d_in[14];
    const float* be1 = (const float*)d_in[15];
    const float* g2  = (const float*)d_in[16];
    const float* be2 = (const float*)d_in[17];
    float* out = (float*)d_out;

    float *v, *ctx, *x1, *hb;
    __half *qh, *kh, *vt;
    cudaGetSymbolAddress((void**)&v, g_v);
    cudaGetSymbolAddress((void**)&ctx, g_ctx);
    cudaGetSymbolAddress((void**)&x1, g_x1);
    cudaGetSymbolAddress((void**)&hb, g_hb);
    cudaGetSymbolAddress((void**)&qh, g_qh);
    cudaGetSymbolAddress((void**)&kh, g_kh);
    cudaGetSymbolAddress((void**)&vt, g_vt);

    cudaFuncSetAttribute(tgemm_kernel<1>, cudaFuncAttributeMaxDynamicSharedMemorySize, GEMM_SMEM_BYTES);
    cudaFuncSetAttribute(tgemm_kernel<2>, cudaFuncAttributeMaxDynamicSharedMemorySize, GEMM_SMEM_BYTES);
    cudaFuncSetAttribute(tgemm_qkv_kernel, cudaFuncAttributeMaxDynamicSharedMemorySize, GEMM_SMEM_BYTES);
    cudaFuncSetAttribute(flash_fp16_kernel, cudaFuncAttributeMaxDynamicSharedMemorySize, FLASH_SMEM_BYTES);

    const dim3 blk(256);
    const dim3 gQKV(D_ / 128, NTOK / 128, 3);
    const dim3 gD(D_ / 128, NTOK / 128);
    const dim3 gFF(FF_ / 128, NTOK / 128);

    // QKV projections: q,k -> fp16; v -> fp32
    tgemm_qkv_kernel<<<gQKV, blk, GEMM_SMEM_BYTES>>>(x, wq, bq, qh, wk, bk, kh, wv, bv, v);

    // V transpose-convert
    vtrans_kernel<<<dim3(D_ / 32, NTOK / 32), dim3(32, 8)>>>(v, vt);

    // Flash attention -> ctx
    flash_fp16_kernel<<<dim3(S_ / 128, B_ * H_), blk, FLASH_SMEM_BYTES>>>(qh, kh, vt, mask, ctx);

    // atted = ctx @ wm + bm; y1 = x + atted  (into g_v, reused)
    tgemm_kernel<2><<<gD, blk, GEMM_SMEM_BYTES>>>(ctx, wm, bm, x, v, NTOK, D_, D_);
    ln_kernel<<<NTOK, blk>>>(v, g1, be1, x1);

    // FFN
    tgemm_kernel<1><<<gFF, blk, GEMM_SMEM_BYTES>>>(x1, w1, b1, nullptr, hb, NTOK, FF_, D_);
    tgemm_kernel<2><<<gD, blk, GEMM_SMEM_BYTES>>>(hb, w2, b2, x1, ctx, NTOK, D_, FF_);
    ln_kernel<<<NTOK, blk>>>(ctx, g2, be2, out);
}

// round 9
// speedup vs baseline: 7.2655x; 1.4530x over previous
#include <cuda_runtime.h>
#include <cuda_fp16.h>
#include <math.h>
#include <stdint.h>

// Problem constants
#define B_   4
#define S_   2048
#define D_   1024
#define H_   16
#define DH_  64
#define FF_  4096
#define NTOK (B_ * S_)   // 8192

// ---------------------------------------------------------------------------
// Scratch buffers
// ---------------------------------------------------------------------------
__device__ float  g_y1[(size_t)NTOK * D_];    // proj+res out; reused for ffn2 out
__device__ float  g_x1[(size_t)NTOK * D_];
__device__ __half g_xh[(size_t)NTOK * D_];
__device__ __half g_wh[(size_t)12 * 1024 * 1024];  // wq,wk,wv,wm (1M ea), w1 (4M), w2 (4M)
__device__ __half g_qh[(size_t)NTOK * D_];
__device__ __half g_kh[(size_t)NTOK * D_];
__device__ __half g_vh[(size_t)NTOK * D_];
__device__ __half g_vt[(size_t)NTOK * D_];    // [b*H+h][64 dh][2048 s]
__device__ __half g_ctxh[(size_t)NTOK * D_];
__device__ __half g_x1h[(size_t)NTOK * D_];
__device__ __half g_hbh[(size_t)NTOK * FF_];

// ---------------------------------------------------------------------------
// helpers
// ---------------------------------------------------------------------------
__device__ __forceinline__ void mma_f16(float* d, const uint32_t* a, const uint32_t* b) {
    asm volatile(
        "mma.sync.aligned.m16n8k16.row.col.f32.f16.f16.f32 "
        "{%0,%1,%2,%3}, {%4,%5,%6,%7}, {%8,%9}, {%0,%1,%2,%3};"
        : "+f"(d[0]), "+f"(d[1]), "+f"(d[2]), "+f"(d[3])
        : "r"(a[0]), "r"(a[1]), "r"(a[2]), "r"(a[3]), "r"(b[0]), "r"(b[1]));
}

__device__ __forceinline__ uint32_t smem_u32(const void* p) {
    uint32_t a;
    asm("{ .reg .u64 t; cvta.to.shared.u64 t, %1; cvt.u32.u64 %0, t; }" : "=r"(a) : "l"(p));
    return a;
}

__device__ __forceinline__ void cpasync16(uint32_t dst, const void* src) {
    asm volatile("cp.async.cg.shared.global [%0], [%1], 16;" :: "r"(dst), "l"(src) : "memory");
}
__device__ __forceinline__ void cpasync_commit() {
    asm volatile("cp.async.commit_group;" ::: "memory");
}
template <int N>
__device__ __forceinline__ void cpasync_wait() {
    asm volatile("cp.async.wait_group %0;" :: "n"(N) : "memory");
}

__device__ __forceinline__ void ldsm_x4(uint32_t* r, uint32_t addr) {
    asm volatile("ldmatrix.sync.aligned.m8n8.x4.shared.b16 {%0,%1,%2,%3}, [%4];"
                 : "=r"(r[0]), "=r"(r[1]), "=r"(r[2]), "=r"(r[3]) : "r"(addr));
}
__device__ __forceinline__ void ldsm_x4_t(uint32_t* r, uint32_t addr) {
    asm volatile("ldmatrix.sync.aligned.m8n8.x4.trans.shared.b16 {%0,%1,%2,%3}, [%4];"
                 : "=r"(r[0]), "=r"(r[1]), "=r"(r[2]), "=r"(r[3]) : "r"(addr));
}

__device__ __forceinline__ uint32_t h2u(__half2 h) {
    return *reinterpret_cast<uint32_t*>(&h);
}

// ---------------------------------------------------------------------------
// fp32 -> fp16 convert (grid-stride-free; n multiple of 1024)
// ---------------------------------------------------------------------------
__global__ __launch_bounds__(256) void f2h_kernel(
    const float* __restrict__ src, __half* __restrict__ dst)
{
    const int i = (blockIdx.x * 256 + threadIdx.x) * 4;
    float4 v = *(const float4*)(src + i);
    *(__half2*)(dst + i)     = __floats2half2_rn(v.x, v.y);
    *(__half2*)(dst + i + 2) = __floats2half2_rn(v.z, v.w);
}

// ---------------------------------------------------------------------------
// fp16 GEMM, cp.async 4-stage + ldmatrix. C[M,N] = A@W + bias (+relu/+res)
// CTA 128x128x32, 256 thr (8 warps 2x4), warp tile 64x32, m16n8k16.
// A stage [128][32] halfs (64B rows, swz chunk^((row>>1)&3))
// B stage [32][128] halfs (256B rows, swz chunk^(krow&7))
// ---------------------------------------------------------------------------
#define GK 32
#define ASTG (128 * 32)
#define BSTG (32 * 128)
#define STGH (ASTG + BSTG)              // 8192 halfs = 16 KB
#define NSTG 4
#define GEMM_SMEM_BYTES (NSTG * STGH * 2)   // 65536

template <int EPI, bool HOUT>
__device__ __forceinline__ void hgemm_body(
    const __half* __restrict__ A, const __half* __restrict__ W,
    const float* __restrict__ bias, const float* __restrict__ res,
    void* __restrict__ Cv, int M, int N, int K)
{
    extern __shared__ __half hsm[];
    const uint32_t sbase = smem_u32(hsm);

    const int tid = threadIdx.x;
    const int lane = tid & 31;
    const int warp = tid >> 5;
    const int wm = warp >> 2;
    const int wn = warp & 3;
    const int bm = blockIdx.y * 128;
    const int bn = blockIdx.x * 128;

    // cp.async fill coords (2 A chunks + 2 B chunks per thread per stage)
    const int ar0 = tid >> 2;          // A rows ar0, ar0+64
    const int akc = tid & 3;           // A k-chunk (16B)
    const int bkr = tid >> 4;          // B k-rows bkr, bkr+16
    const int bnc = tid & 15;          // B n-chunk (16B)

    const __half* Ag = A + (size_t)bm * K;
    const __half* Wg = W + bn;

    // precomputed A fill offsets (swizzle)
    const uint32_t a_off1 = (uint32_t)(ar0 * 64 + ((akc ^ ((ar0 >> 1) & 3)) << 4));
    const uint32_t a_off2 = (uint32_t)((ar0 + 64) * 64 + ((akc ^ (((ar0 + 64) >> 1) & 3)) << 4));
    const uint32_t b_off1 = (uint32_t)(bkr * 256 + ((bnc ^ (bkr & 7)) << 4));
    const uint32_t b_off2 = (uint32_t)((bkr + 16) * 256 + ((bnc ^ ((bkr + 16) & 7)) << 4));

    // ldmatrix A coords
    uint32_t a_row_off[4];
    int a_row_sw[4];
#pragma unroll
    for (int i = 0; i < 4; i++) {
        const int row = wm * 64 + i * 16 + (lane & 15);
        a_row_off[i] = (uint32_t)(row * 64);
        a_row_sw[i] = (row >> 1) & 3;
    }
    const int a_csel = lane >> 4;           // 0/1
    // ldmatrix B coords
    const int b_krlo = lane & 15;
    const int b_ncsel = wn * 4 + (lane >> 4);  // + jj*2

    float acc[4][4][4];
#pragma unroll
    for (int i = 0; i < 4; i++)
#pragma unroll
        for (int j = 0; j < 4; j++)
#pragma unroll
            for (int r = 0; r < 4; r++) acc[i][j][r] = 0.f;

    const int NIT = K / GK;

    // stage issue macro-ish lambda
    auto issue = [&](int s, int k0) {
        const uint32_t ab = sbase + (uint32_t)(s * STGH) * 2;
        const uint32_t bb = ab + ASTG * 2;
        cpasync16(ab + a_off1, Ag + (size_t)ar0 * K + k0 + akc * 8);
        cpasync16(ab + a_off2, Ag + (size_t)(ar0 + 64) * K + k0 + akc * 8);
        cpasync16(bb + b_off1, Wg + (size_t)(k0 + bkr) * N + bnc * 8);
        cpasync16(bb + b_off2, Wg + (size_t)(k0 + bkr + 16) * N + bnc * 8);
        cpasync_commit();
    };

    issue(0, 0);
    issue(1, GK);
    issue(2, 2 * GK);

    for (int t = 0; t < NIT; t++) {
        if (t + 3 < NIT) { issue((t + 3) & 3, (t + 3) * GK); cpasync_wait<3>(); }
        else if (t + 2 < NIT) cpasync_wait<2>();
        else if (t + 1 < NIT) cpasync_wait<1>();
        else cpasync_wait<0>();
        __syncthreads();

        const uint32_t ab = sbase + (uint32_t)((t & 3) * STGH) * 2;
        const uint32_t bb = ab + ASTG * 2;

#pragma unroll
        for (int ksb = 0; ksb < 2; ksb++) {
            uint32_t av[4][4];
#pragma unroll
            for (int i = 0; i < 4; i++) {
                const int lch = ksb * 2 + a_csel;
                ldsm_x4(av[i], ab + a_row_off[i] + (uint32_t)((lch ^ a_row_sw[i]) << 4));
            }
            uint32_t bf[4][2];
#pragma unroll
            for (int jj = 0; jj < 2; jj++) {
                uint32_t tmp[4];
                const int krow = ksb * 16 + b_krlo;
                const int nch = b_ncsel + jj * 2;
                ldsm_x4_t(tmp, bb + (uint32_t)(krow * 256) + (uint32_t)((nch ^ (krow & 7)) << 4));
                bf[jj * 2][0] = tmp[0]; bf[jj * 2][1] = tmp[1];
                bf[jj * 2 + 1][0] = tmp[2]; bf[jj * 2 + 1][1] = tmp[3];
            }
#pragma unroll
            for (int i = 0; i < 4; i++)
#pragma unroll
                for (int j = 0; j < 4; j++)
                    mma_f16(acc[i][j], av[i], bf[j]);
        }
        __syncthreads();
    }

    // Epilogue
#pragma unroll
    for (int i = 0; i < 4; i++) {
        const int r0 = bm + wm * 64 + i * 16 + (lane >> 2);
#pragma unroll
        for (int j = 0; j < 4; j++) {
            const int col = bn + wn * 32 + j * 8 + (lane & 3) * 2;
            float2 bi = *(const float2*)(bias + col);
            float o00 = acc[i][j][0] + bi.x;
            float o01 = acc[i][j][1] + bi.y;
            float o10 = acc[i][j][2] + bi.x;
            float o11 = acc[i][j][3] + bi.y;
            if (EPI == 1) {
                o00 = fmaxf(o00, 0.f); o01 = fmaxf(o01, 0.f);
                o10 = fmaxf(o10, 0.f); o11 = fmaxf(o11, 0.f);
            }
            if (EPI == 2) {
                float2 r0v = *(const float2*)(res + (size_t)r0 * N + col);
                float2 r1v = *(const float2*)(res + (size_t)(r0 + 8) * N + col);
                o00 += r0v.x; o01 += r0v.y;
                o10 += r1v.x; o11 += r1v.y;
            }
            if (HOUT) {
                __half* Ch = (__half*)Cv;
                *(__half2*)(Ch + (size_t)r0 * N + col) = __floats2half2_rn(o00, o01);
                *(__half2*)(Ch + (size_t)(r0 + 8) * N + col) = __floats2half2_rn(o10, o11);
            } else {
                float* Cf = (float*)Cv;
                *(float2*)(Cf + (size_t)r0 * N + col) = make_float2(o00, o01);
                *(float2*)(Cf + (size_t)(r0 + 8) * N + col) = make_float2(o10, o11);
            }
        }
    }
}

template <int EPI, bool HOUT>
__global__ __launch_bounds__(256, 2) void hgemm_kernel(
    const __half* __restrict__ A, const __half* __restrict__ W,
    const float* __restrict__ bias, const float* __restrict__ res,
    void* __restrict__ C, int M, int N, int K)
{
    hgemm_body<EPI, HOUT>(A, W, bias, res, C, M, N, K);
}

__global__ __launch_bounds__(256, 2) void hgemm_qkv_kernel(
    const __half* __restrict__ xh,
    const __half* __restrict__ wq, const float* __restrict__ bq, __half* __restrict__ qh,
    const __half* __restrict__ wk, const float* __restrict__ bk, __half* __restrict__ kh,
    const __half* __restrict__ wv, const float* __restrict__ bv, __half* __restrict__ vh)
{
    if (blockIdx.z == 0)      hgemm_body<0, true>(xh, wq, bq, nullptr, qh, NTOK, D_, D_);
    else if (blockIdx.z == 1) hgemm_body<0, true>(xh, wk, bk, nullptr, kh, NTOK, D_, D_);
    else                      hgemm_body<0, true>(xh, wv, bv, nullptr, vh, NTOK, D_, D_);
}

// ---------------------------------------------------------------------------
// V transpose: g_vh fp16 [tok][D] -> g_vt fp16 [b*H+h][dh][s]
// ---------------------------------------------------------------------------
__global__ __launch_bounds__(256) void vtrans_kernel(
    const __half* __restrict__ v, __half* __restrict__ vt)
{
    __shared__ __half t[32][33];
    const int c0 = blockIdx.x * 32;
    const int r0 = blockIdx.y * 32;
    const int x = threadIdx.x, y = threadIdx.y;
#pragma unroll
    for (int i = 0; i < 32; i += 8)
        t[y + i][x] = v[(size_t)(r0 + y + i) * D_ + c0 + x];
    __syncthreads();
    const int b = r0 >> 11;
    const int s = (r0 & 2047) + x;
    const int h = c0 >> 6;
    const int d0 = c0 & 63;
#pragma unroll
    for (int i = 0; i < 32; i += 8) {
        const int d = d0 + y + i;
        vt[((size_t)(b * 16 + h) * 64 + d) * (size_t)S_ + s] = t[x][y + i];
    }
}

// ---------------------------------------------------------------------------
// fp16 flash attention (round-8 design; ctx now written fp16)
// ---------------------------------------------------------------------------
#define FBK 64
#define KROW 72
#define KBUF (64 * KROW)
#define NSTAGE 3
#define FLASH_SMEM_BYTES (NSTAGE * 2 * KBUF * 2)

__global__ __launch_bounds__(256, 2) void flash_fp16_kernel(
    const __half* __restrict__ qh, const __half* __restrict__ kh,
    const __half* __restrict__ vt, const unsigned char* __restrict__ mask,
    __half* __restrict__ ctxh)
{
    extern __shared__ __half fh[];
    __half* Kf = fh;
    __half* Vf = fh + NSTAGE * KBUF;
    const uint32_t ks_u = smem_u32(Kf);
    const uint32_t vs_u = smem_u32(Vf);

    const int tid = threadIdx.x;
    const int lane = tid & 31;
    const int warp = tid >> 5;
    const int bh = blockIdx.y;
    const int b = bh >> 4;
    const int h = bh & 15;
    const int q0 = blockIdx.x * 128;
    const int hoff = h * DH_;
    const unsigned char* mrow = mask + (size_t)b * S_;

    const int r0 = lane >> 2;
    const int c0 = lane & 3;

    uint32_t qf[4][4];
    {
        const size_t rowa = (size_t)(b * S_ + q0 + warp * 16 + r0) * D_ + hoff;
#pragma unroll
        for (int ks = 0; ks < 4; ks++) {
            const int c = ks * 16 + 2 * c0;
            qf[ks][0] = *(const uint32_t*)(qh + rowa + c);
            qf[ks][1] = *(const uint32_t*)(qh + rowa + 8 * D_ + c);
            qf[ks][2] = *(const uint32_t*)(qh + rowa + c + 8);
            qf[ks][3] = *(const uint32_t*)(qh + rowa + 8 * D_ + c + 8);
        }
    }

    float oa[8][4];
    float mx0 = -1e30f, mx1 = -1e30f, l0 = 0.f, l1 = 0.f;
#pragma unroll
    for (int j = 0; j < 8; j++)
#pragma unroll
        for (int r = 0; r < 4; r++) oa[j][r] = 0.f;

    const int id0 = tid, id1 = tid + 256;
    const int krow0 = id0 >> 3, kch0 = id0 & 7;
    const int krow1 = id1 >> 3, kch1 = id1 & 7;

    const __half* kbase = kh + (size_t)b * S_ * D_ + hoff;
    const __half* vbase = vt + (size_t)bh * 64 * S_;

    const int NT = S_ / FBK;

#pragma unroll
    for (int t = 0; t < 2; t++) {
        const int kt = t * FBK;
        const uint32_t kdst = ks_u + (uint32_t)(t * KBUF) * 2;
        const uint32_t vdst = vs_u + (uint32_t)(t * KBUF) * 2;
        cpasync16(kdst + (uint32_t)(krow0 * KROW) * 2 + kch0 * 16,
                  kbase + (size_t)(kt + krow0) * D_ + kch0 * 8);
        cpasync16(kdst + (uint32_t)(krow1 * KROW) * 2 + kch1 * 16,
                  kbase + (size_t)(kt + krow1) * D_ + kch1 * 8);
        cpasync16(vdst + (uint32_t)(krow0 * KROW) * 2 + kch0 * 16,
                  vbase + (size_t)krow0 * S_ + kt + kch0 * 8);
        cpasync16(vdst + (uint32_t)(krow1 * KROW) * 2 + kch1 * 16,
                  vbase + (size_t)krow1 * S_ + kt + kch1 * 8);
        cpasync_commit();
    }

    for (int t = 0; t < NT; t++) {
        const int kt = t * FBK;
        if (t + 2 < NT) {
            const int nkt = kt + 2 * FBK;
            const int st = (t + 2) % NSTAGE;
            const uint32_t kdst = ks_u + (uint32_t)(st * KBUF) * 2;
            const uint32_t vdst = vs_u + (uint32_t)(st * KBUF) * 2;
            cpasync16(kdst + (uint32_t)(krow0 * KROW) * 2 + kch0 * 16,
                      kbase + (size_t)(nkt + krow0) * D_ + kch0 * 8);
            cpasync16(kdst + (uint32_t)(krow1 * KROW) * 2 + kch1 * 16,
                      kbase + (size_t)(nkt + krow1) * D_ + kch1 * 8);
            cpasync16(vdst + (uint32_t)(krow0 * KROW) * 2 + kch0 * 16,
                      vbase + (size_t)krow0 * S_ + nkt + kch0 * 8);
            cpasync16(vdst + (uint32_t)(krow1 * KROW) * 2 + kch1 * 16,
                      vbase + (size_t)krow1 * S_ + nkt + kch1 * 8);
            cpasync_commit();
            cpasync_wait<2>();
        } else if (t + 1 < NT) {
            cpasync_wait<1>();
        } else {
            cpasync_wait<0>();
        }
        __syncthreads();

        const __half* Kc = Kf + (t % NSTAGE) * KBUF;
        const __half* Vc = Vf + (t % NSTAGE) * KBUF;

        float sa[8][4];
#pragma unroll
        for (int j = 0; j < 8; j++)
#pragma unroll
            for (int r = 0; r < 4; r++) sa[j][r] = 0.f;

#pragma unroll
        for (int ks = 0; ks < 4; ks++) {
            const int kc = ks * 16 + 2 * c0;
#pragma unroll
            for (int j = 0; j < 8; j++) {
                const __half* kp = Kc + (j * 8 + r0) * KROW + kc;
                uint32_t bb[2];
                bb[0] = *(const uint32_t*)kp;
                bb[1] = *(const uint32_t*)(kp + 8);
                mma_f16(sa[j], qf[ks], bb);
            }
        }

        float rm0 = -1e30f, rm1 = -1e30f;
#pragma unroll
        for (int j = 0; j < 8; j++) {
            const int col = kt + j * 8 + 2 * c0;
            const bool m0 = mrow[col] != 0;
            const bool m1 = mrow[col + 1] != 0;
            sa[j][0] = m0 ? -1e9f : sa[j][0] * 0.125f;
            sa[j][1] = m1 ? -1e9f : sa[j][1] * 0.125f;
            sa[j][2] = m0 ? -1e9f : sa[j][2] * 0.125f;
            sa[j][3] = m1 ? -1e9f : sa[j][3] * 0.125f;
            rm0 = fmaxf(rm0, fmaxf(sa[j][0], sa[j][1]));
            rm1 = fmaxf(rm1, fmaxf(sa[j][2], sa[j][3]));
        }
        rm0 = fmaxf(rm0, __shfl_xor_sync(0xffffffffu, rm0, 1));
        rm0 = fmaxf(rm0, __shfl_xor_sync(0xffffffffu, rm0, 2));
        rm1 = fmaxf(rm1, __shfl_xor_sync(0xffffffffu, rm1, 1));
        rm1 = fmaxf(rm1, __shfl_xor_sync(0xffffffffu, rm1, 2));

        const float mn0 = fmaxf(mx0, rm0);
        const float mn1 = fmaxf(mx1, rm1);
        const float corr0 = __expf(mx0 - mn0);
        const float corr1 = __expf(mx1 - mn1);
        mx0 = mn0; mx1 = mn1;

        float rs0 = 0.f, rs1 = 0.f;
#pragma unroll
        for (int j = 0; j < 8; j++) {
            sa[j][0] = __expf(sa[j][0] - mn0);
            sa[j][1] = __expf(sa[j][1] - mn0);
            sa[j][2] = __expf(sa[j][2] - mn1);
            sa[j][3] = __expf(sa[j][3] - mn1);
            rs0 += sa[j][0] + sa[j][1];
            rs1 += sa[j][2] + sa[j][3];
            oa[j][0] *= corr0; oa[j][1] *= corr0;
            oa[j][2] *= corr1; oa[j][3] *= corr1;
        }
        rs0 += __shfl_xor_sync(0xffffffffu, rs0, 1);
        rs0 += __shfl_xor_sync(0xffffffffu, rs0, 2);
        rs1 += __shfl_xor_sync(0xffffffffu, rs1, 1);
        rs1 += __shfl_xor_sync(0xffffffffu, rs1, 2);
        l0 = l0 * corr0 + rs0;
        l1 = l1 * corr1 + rs1;

#pragma unroll
        for (int ks = 0; ks < 4; ks++) {
            uint32_t pf[4];
            pf[0] = h2u(__floats2half2_rn(sa[2 * ks][0], sa[2 * ks][1]));
            pf[1] = h2u(__floats2half2_rn(sa[2 * ks][2], sa[2 * ks][3]));
            pf[2] = h2u(__floats2half2_rn(sa[2 * ks + 1][0], sa[2 * ks + 1][1]));
            pf[3] = h2u(__floats2half2_rn(sa[2 * ks + 1][2], sa[2 * ks + 1][3]));
            const int kc = ks * 16 + 2 * c0;
#pragma unroll
            for (int j = 0; j < 8; j++) {
                const __half* vp = Vc + (j * 8 + r0) * KROW + kc;
                uint32_t bb[2];
                bb[0] = *(const uint32_t*)vp;
                bb[1] = *(const uint32_t*)(vp + 8);
                mma_f16(oa[j], pf, bb);
            }
        }

        __syncthreads();
    }

    const float inv0 = 1.f / l0;
    const float inv1 = 1.f / l1;
    const int row0 = q0 + warp * 16 + r0;
    const size_t obase = (size_t)b * S_ * D_ + hoff;
#pragma unroll
    for (int j = 0; j < 8; j++) {
        const int col = j * 8 + 2 * c0;
        *(__half2*)(ctxh + obase + (size_t)row0 * D_ + col) =
            __floats2half2_rn(oa[j][0] * inv0, oa[j][1] * inv0);
        *(__half2*)(ctxh + obase + (size_t)(row0 + 8) * D_ + col) =
            __floats2half2_rn(oa[j][2] * inv1, oa[j][3] * inv1);
    }
}

// ---------------------------------------------------------------------------
// LayerNorm: fp32 in -> fp32 out (+ optional fp16 out)
// ---------------------------------------------------------------------------
__global__ __launch_bounds__(256) void ln_kernel(
    const float* __restrict__ in, const float* __restrict__ g,
    const float* __restrict__ be, float* __restrict__ out,
    __half* __restrict__ outh)
{
    __shared__ float sred[8], ssred[8];
    __shared__ float muSh, rsSh;

    const int row = blockIdx.x;
    const int tid = threadIdx.x;
    const int lane = tid & 31;
    const int wid = tid >> 5;

    const float* p = in + (size_t)row * D_;
    float4 x = *(const float4*)(p + tid * 4);
    float s = x.x + x.y + x.z + x.w;
    float ss = x.x * x.x + x.y * x.y + x.z * x.z + x.w * x.w;

#pragma unroll
    for (int off = 16; off > 0; off >>= 1) {
        s += __shfl_xor_sync(0xffffffffu, s, off);
        ss += __shfl_xor_sync(0xffffffffu, ss, off);
    }
    if (lane == 0) { sred[wid] = s; ssred[wid] = ss; }
    __syncthreads();
    if (wid == 0) {
        float s2 = (lane < 8) ? sred[lane] : 0.f;
        float ss2 = (lane < 8) ? ssred[lane] : 0.f;
#pragma unroll
        for (int off = 4; off > 0; off >>= 1) {
            s2 += __shfl_xor_sync(0xffffffffu, s2, off);
            ss2 += __shfl_xor_sync(0xffffffffu, ss2, off);
        }
        if (lane == 0) {
            const float mu = s2 * (1.f / D_);
            const float var = ss2 * (1.f / D_) - mu * mu;
            muSh = mu;
            rsSh = rsqrtf(var + 1e-6f);
        }
    }
    __syncthreads();

    const float mu = muSh, rs = rsSh;
    float4 gg = *(const float4*)(g + tid * 4);
    float4 bb = *(const float4*)(be + tid * 4);
    float4 y;
    y.x = (x.x - mu) * rs * gg.x + bb.x;
    y.y = (x.y - mu) * rs * gg.y + bb.y;
    y.z = (x.z - mu) * rs * gg.z + bb.z;
    y.w = (x.w - mu) * rs * gg.w + bb.w;
    *(float4*)(out + (size_t)row * D_ + tid * 4) = y;
    if (outh) {
        *(__half2*)(outh + (size_t)row * D_ + tid * 4)     = __floats2half2_rn(y.x, y.y);
        *(__half2*)(outh + (size_t)row * D_ + tid * 4 + 2) = __floats2half2_rn(y.z, y.w);
    }
}

// ---------------------------------------------------------------------------
// Launch
// ---------------------------------------------------------------------------
extern "C" void kernel_launch(void* const* d_in, const int* in_sizes, int n_in,
                              void* d_out, int out_size)
{
    const float* x   = (const float*)d_in[0];
    const unsigned char* mask = (const unsigned char*)d_in[1];
    const float* wq = (const float*)d_in[2];
    const float* bq = (const float*)d_in[3];
    const float* wk = (const float*)d_in[4];
    const float* bk = (const float*)d_in[5];
    const float* wv = (const float*)d_in[6];
    const float* bv = (const float*)d_in[7];
    const float* wm = (const float*)d_in[8];
    const float* bm = (const float*)d_in[9];
    const float* w1 = (const float*)d_in[10];
    const float* b1 = (const float*)d_in[11];
    const float* w2 = (const float*)d_in[12];
    const float* b2 = (const float*)d_in[13];
    const float* g1  = (const float*)d_in[14];
    const float* be1 = (const float*)d_in[15];
    const float* g2  = (const float*)d_in[16];
    const float* be2 = (const float*)d_in[17];
    float* out = (float*)d_out;

    float *y1, *x1;
    __half *xh, *wh, *qh, *kh, *vh, *vt, *ctxh, *x1h, *hbh;
    cudaGetSymbolAddress((void**)&y1, g_y1);
    cudaGetSymbolAddress((void**)&x1, g_x1);
    cudaGetSymbolAddress((void**)&xh, g_xh);
    cudaGetSymbolAddress((void**)&wh, g_wh);
    cudaGetSymbolAddress((void**)&qh, g_qh);
    cudaGetSymbolAddress((void**)&kh, g_kh);
    cudaGetSymbolAddress((void**)&vh, g_vh);
    cudaGetSymbolAddress((void**)&vt, g_vt);
    cudaGetSymbolAddress((void**)&ctxh, g_ctxh);
    cudaGetSymbolAddress((void**)&x1h, g_x1h);
    cudaGetSymbolAddress((void**)&hbh, g_hbh);

    __half* whq = wh;
    __half* whk = wh + (size_t)1 * 1024 * 1024;
    __half* whv = wh + (size_t)2 * 1024 * 1024;
    __half* whm = wh + (size_t)3 * 1024 * 1024;
    __half* wh1 = wh + (size_t)4 * 1024 * 1024;
    __half* wh2 = wh + (size_t)8 * 1024 * 1024;

    cudaFuncSetAttribute(hgemm_kernel<1, true>,  cudaFuncAttributeMaxDynamicSharedMemorySize, GEMM_SMEM_BYTES);
    cudaFuncSetAttribute(hgemm_kernel<2, false>, cudaFuncAttributeMaxDynamicSharedMemorySize, GEMM_SMEM_BYTES);
    cudaFuncSetAttribute(hgemm_qkv_kernel, cudaFuncAttributeMaxDynamicSharedMemorySize, GEMM_SMEM_BYTES);
    cudaFuncSetAttribute(flash_fp16_kernel, cudaFuncAttributeMaxDynamicSharedMemorySize, FLASH_SMEM_BYTES);

    const dim3 blk(256);

    // fp32 -> fp16 pre-pass (x + 6 weights)
    f2h_kernel<<<NTOK * D_ / 1024, blk>>>(x, xh);
    f2h_kernel<<<1024, blk>>>(wq, whq);
    f2h_kernel<<<1024, blk>>>(wk, whk);
    f2h_kernel<<<1024, blk>>>(wv, whv);
    f2h_kernel<<<1024, blk>>>(wm, whm);
    f2h_kernel<<<4096, blk>>>(w1, wh1);
    f2h_kernel<<<4096, blk>>>(w2, wh2);

    const dim3 gQKV(D_ / 128, NTOK / 128, 3);
    const dim3 gD(D_ / 128, NTOK / 128);
    const dim3 gFF(FF_ / 128, NTOK / 128);

    // QKV projections (all fp16 out)
    hgemm_qkv_kernel<<<gQKV, blk, GEMM_SMEM_BYTES>>>(xh, whq, bq, qh, whk, bk, kh, whv, bv, vh);

    // V transpose
    vtrans_kernel<<<dim3(D_ / 32, NTOK / 32), dim3(32, 8)>>>(vh, vt);

    // Flash attention -> ctxh (fp16)
    flash_fp16_kernel<<<dim3(S_ / 128, B_ * H_), blk, FLASH_SMEM_BYTES>>>(qh, kh, vt, mask, ctxh);

    // proj + residual -> y1 (fp32)
    hgemm_kernel<2, false><<<gD, blk, GEMM_SMEM_BYTES>>>(ctxh, whm, bm, x, y1, NTOK, D_, D_);
    ln_kernel<<<NTOK, blk>>>(y1, g1, be1, x1, x1h);

    // FFN
    hgemm_kernel<1, true><<<gFF, blk, GEMM_SMEM_BYTES>>>(x1h, wh1, b1, nullptr, hbh, NTOK, FF_, D_);
    hgemm_kernel<2, false><<<gD, blk, GEMM_SMEM_BYTES>>>(hbh, wh2, b2, x1, y1, NTOK, D_, FF_);
    ln_kernel<<<NTOK, blk>>>(y1, g2, be2, out, nullptr);
}